// round 14
// baseline (speedup 1.0000x reference)
#include <cuda_runtime.h>
#include <cuda_fp16.h>
#include <mma.h>
#include <math.h>

using namespace nvcuda;

#define N_NODES 38332
#define N_PAD   38400
#define POI_LEN_ 38333
#define POI_DIM 300
#define CAT_DIM 100
#define FEAT_DIM 403
#define CCH 128
#define NLAYERS 5
#define NEDGES 1200000
#define TOTE (NEDGES + N_NODES)
#define NEG 0.01f
#define GAT_NEG 0.2f

// ---------------- scratch (static __device__, no allocation) ----------------
__device__ float  d_feat[N_NODES * FEAT_DIM];
__device__ float  d_x [N_NODES * CCH];
__device__ __half d_xwh[N_PAD * CCH];
__device__ float  d_y [N_NODES * CCH];
__device__ int    d_csr_src [TOTE];
__device__ float  d_csr_w   [TOTE];
__device__ float  d_csr_norm[TOTE];
__device__ int    d_row_ptr[N_NODES + 1];
__device__ int    d_cnt   [N_NODES];
__device__ int    d_cursor[N_NODES];
__device__ float  d_dinv[N_NODES];
__device__ float  d_al [N_NODES];
__device__ float  d_ar [N_NODES];
__device__ float  d_xw1[N_NODES];
__device__ float  d_xs [N_NODES];
__device__ float  d_stat[2 * CCH];
__device__ float  d_shift[CCH];
__device__ float  d_rstd [CCH];
__device__ float  d_hraw[CCH];
__device__ float  d_h   [CCH];

__device__ __forceinline__ float leaky01(float v) { return v > 0.f ? v : NEG * v; }
__device__ __forceinline__ float leaky20(float v) { return v > 0.f ? v : GAT_NEG * v; }

__device__ __forceinline__ float4 h4_to_f4(uint2 u) {
    float4 r;
    asm("{\n\t"
        ".reg .b16 a, b, c, d;\n\t"
        "mov.b32 {a, b}, %4;\n\t"
        "mov.b32 {c, d}, %5;\n\t"
        "cvt.f32.f16 %0, a;\n\t"
        "cvt.f32.f16 %1, b;\n\t"
        "cvt.f32.f16 %2, c;\n\t"
        "cvt.f32.f16 %3, d;\n\t"
        "}"
        : "=f"(r.x), "=f"(r.y), "=f"(r.z), "=f"(r.w)
        : "r"(u.x), "r"(u.y));
    return r;
}

__device__ __forceinline__ uint2 f4_to_h4(float4 v) {
    __half2 h0 = __floats2half2_rn(v.x, v.y);
    __half2 h1 = __floats2half2_rn(v.z, v.w);
    return make_uint2(*(unsigned*)&h0, *(unsigned*)&h1);
}

// accumulate 8 fp16 channels (uint4) into two float4 accs with scalar weight
__device__ __forceinline__ void fma8(float4& a0, float4& a1, uint4 u, float w) {
    float4 v0 = h4_to_f4(make_uint2(u.x, u.y));
    a0.x += w * v0.x; a0.y += w * v0.y; a0.z += w * v0.z; a0.w += w * v0.w;
    float4 v1 = h4_to_f4(make_uint2(u.z, u.w));
    a1.x += w * v1.x; a1.y += w * v1.y; a1.z += w * v1.z; a1.w += w * v1.w;
}

// ---------------- CSR build ----------------
__global__ void init_k() {
    int i = blockIdx.x * blockDim.x + threadIdx.x;
    if (i < N_NODES) d_cnt[i] = 1;
    if (i < CCH)     d_hraw[i] = 0.f;
    if (i < 2 * CCH) d_stat[i] = 0.f;
}

__global__ void hist_k(const int* __restrict__ ei) {
    int e = blockIdx.x * blockDim.x + threadIdx.x;
    if (e < NEDGES) atomicAdd(&d_cnt[ei[NEDGES + e]], 1);
}

__global__ void scan_k() {
    const int T = 1024;
    const int ITEMS = (N_NODES + T - 1) / T;
    int tid = threadIdx.x;
    int start = tid * ITEMS;
    int end   = min(start + ITEMS, N_NODES);
    int s = 0;
    for (int i = start; i < end; i++) s += d_cnt[i];
    __shared__ int ps[T];
    ps[tid] = s; __syncthreads();
    for (int off = 1; off < T; off <<= 1) {
        int v = (tid >= off) ? ps[tid - off] : 0;
        __syncthreads();
        ps[tid] += v;
        __syncthreads();
    }
    int incl = ps[tid];
    int run  = incl - s;
    for (int i = start; i < end; i++) { d_row_ptr[i] = run; run += d_cnt[i]; }
    if (tid == T - 1) d_row_ptr[N_NODES] = incl;
}

__global__ void selfloop_k() {
    int i = blockIdx.x * blockDim.x + threadIdx.x;
    if (i < N_NODES) {
        int p = d_row_ptr[i];
        d_csr_src[p] = i;
        d_csr_w[p]   = 1.0f;
        d_cursor[i]  = p + 1;
    }
}

__global__ void scatter_k(const int* __restrict__ ei, const float* __restrict__ ew) {
    int e = blockIdx.x * blockDim.x + threadIdx.x;
    if (e < NEDGES) {
        int dst = ei[NEDGES + e];
        int p = atomicAdd(&d_cursor[dst], 1);
        d_csr_src[p] = ei[e];
        d_csr_w[p]   = ew[e];
    }
}

__global__ void deg_k() {
    int g = blockIdx.x * blockDim.x + threadIdx.x;
    int node = g >> 5, lane = g & 31;
    if (node >= N_NODES) return;
    int s = d_row_ptr[node], e = d_row_ptr[node + 1];
    float acc = 0.f;
    for (int j = s + lane; j < e; j += 32) acc += d_csr_w[j];
    #pragma unroll
    for (int off = 16; off; off >>= 1) acc += __shfl_down_sync(0xffffffffu, acc, off);
    if (lane == 0) d_dinv[node] = rsqrtf(acc);
}

__global__ void csnorm_k() {
    int g = blockIdx.x * blockDim.x + threadIdx.x;
    int node = g >> 5, lane = g & 31;
    if (node >= N_NODES) return;
    int s = d_row_ptr[node], e = d_row_ptr[node + 1];
    float dv = d_dinv[node];
    for (int j = s + lane; j < e; j += 32)
        d_csr_norm[j] = d_dinv[d_csr_src[j]] * d_csr_w[j] * dv;
}

// ---------------- feature assembly ----------------
__global__ void feat_k(const int* __restrict__ poi_ids, const int* __restrict__ cat_ids,
                       const float* __restrict__ feat3,
                       const float* __restrict__ poi_emb, const float* __restrict__ cat_emb) {
    int node = blockIdx.x, tid = threadIdx.x;
    int pid = poi_ids[node], cid = cat_ids[node];
    float* f = d_feat + (long)node * FEAT_DIM;
    for (int k = tid; k < POI_DIM; k += 128) f[k] = poi_emb[(long)pid * POI_DIM + k];
    for (int k = tid; k < CAT_DIM; k += 128) f[POI_DIM + k] = cat_emb[cid * CAT_DIM + k];
    if (tid < 3) f[400 + tid] = feat3[node * 3 + tid];
}

// ---------------- GEMM (fp16 HMMA, double-buffered, fused norm loader) --------------
#define GM 64
#define GN 128
#define GK 16
#define XS_LD 24
#define WS_LD 136
#define EPI_LD 132

#define XS_BYTES (2 * GM * XS_LD * 2)
#define WS_BYTES (2 * GK * WS_LD * 2)
#define SMEM_BYTES (XS_BYTES + WS_BYTES)

__global__ __launch_bounds__(256) void gemm_h16_db(
    const float* __restrict__ X, const float* __restrict__ W, __half* __restrict__ Yh,
    int n, int K,
    const float* __restrict__ yin, float* __restrict__ xio,
    const float* __restrict__ gamma, const float* __restrict__ beta, int fuse_norm,
    const float* __restrict__ asrc, const float* __restrict__ adst, int fuse_alar) {
    __shared__ __align__(16) char smem_raw[SMEM_BYTES];
    typedef __half XsRow[GM][XS_LD];
    typedef __half WsRow[GK][WS_LD];
    XsRow* Xs = reinterpret_cast<XsRow*>(smem_raw);
    WsRow* Ws = reinterpret_cast<WsRow*>(smem_raw + XS_BYTES);
    float (*Epi)[EPI_LD] = reinterpret_cast<float (*)[EPI_LD]>(smem_raw);
    __shared__ float asS[CCH], adS[CCH];
    __shared__ float gS[CCH], bS[CCH], shS[CCH], rsS[CCH];

    int tid = threadIdx.x;
    int warp = tid >> 5;
    int wm = warp & 1;
    int wn = warp >> 1;
    int row0 = blockIdx.x * GM;

    if (fuse_alar && tid < CCH) { asS[tid] = asrc[tid]; adS[tid] = adst[tid]; }
    if (fuse_norm) {
        if (tid < CCH) {
            gS[tid] = gamma[tid]; bS[tid] = beta[tid];
            shS[tid] = d_shift[tid]; rsS[tid] = d_rstd[tid];
        }
        __syncthreads();
    }

    wmma::fragment<wmma::accumulator, 16, 16, 16, float> c[2][2];
    #pragma unroll
    for (int i = 0; i < 2; i++)
        #pragma unroll
        for (int j = 0; j < 2; j++) wmma::fill_fragment(c[i][j], 0.f);

    int nIter = (K + GK - 1) / GK;

    int rX = tid >> 2;
    int kX = (tid & 3) * 4;
    int gr = row0 + rX;
    uint2 xr; uint2 wr[2];

    auto loadX = [&](int gk0) -> uint2 {
        if (fuse_norm) {
            if (gr < n) {
                size_t off = (size_t)gr * CCH + gk0;
                float4 yv = *(const float4*)(yin + off);
                float4 xv = *(const float4*)(xio + off);
                float4 v;
                v.x = xv.x + leaky01(gS[gk0]     * (yv.x - shS[gk0])     * rsS[gk0]     + bS[gk0]);
                v.y = xv.y + leaky01(gS[gk0 + 1] * (yv.y - shS[gk0 + 1]) * rsS[gk0 + 1] + bS[gk0 + 1]);
                v.z = xv.z + leaky01(gS[gk0 + 2] * (yv.z - shS[gk0 + 2]) * rsS[gk0 + 2] + bS[gk0 + 2]);
                v.w = xv.w + leaky01(gS[gk0 + 3] * (yv.w - shS[gk0 + 3]) * rsS[gk0 + 3] + bS[gk0 + 3]);
                *(float4*)(xio + off) = v;
                return f4_to_h4(v);
            }
            return make_uint2(0u, 0u);
        }
        float xv[4];
        #pragma unroll
        for (int t = 0; t < 4; t++) {
            int gk = gk0 + t;
            xv[t] = (gr < n && gk < K) ? X[(size_t)gr * K + gk] : 0.f;
        }
        return f4_to_h4(make_float4(xv[0], xv[1], xv[2], xv[3]));
    };

    xr = loadX(kX);
    #pragma unroll
    for (int i = 0; i < 2; i++) {
        int e = (tid + i * 256) * 4;
        int rW = e >> 7, cW = e & 127;
        float4 v = (rW < K) ? *(const float4*)(W + (size_t)rW * GN + cW)
                            : make_float4(0.f, 0.f, 0.f, 0.f);
        wr[i] = f4_to_h4(v);
    }

    for (int it = 0; it < nIter; it++) {
        int cur = it & 1;
        *(uint2*)&Xs[cur][rX][kX] = xr;
        #pragma unroll
        for (int i = 0; i < 2; i++) {
            int e = (tid + i * 256) * 4;
            int rW = e >> 7, cW = e & 127;
            *(uint2*)&Ws[cur][rW][cW] = wr[i];
        }
        __syncthreads();
        if (it + 1 < nIter) {
            int k0 = (it + 1) * GK;
            xr = loadX(k0 + kX);
            #pragma unroll
            for (int i = 0; i < 2; i++) {
                int e = (tid + i * 256) * 4;
                int rW = e >> 7, cW = e & 127;
                int gk = k0 + rW;
                float4 v = (gk < K) ? *(const float4*)(W + (size_t)gk * GN + cW)
                                    : make_float4(0.f, 0.f, 0.f, 0.f);
                wr[i] = f4_to_h4(v);
            }
        }
        wmma::fragment<wmma::matrix_a, 16, 16, 16, __half, wmma::row_major> a[2];
        wmma::fragment<wmma::matrix_b, 16, 16, 16, __half, wmma::row_major> bf[2];
        #pragma unroll
        for (int i = 0; i < 2; i++)
            wmma::load_matrix_sync(a[i], &Xs[cur][wm * 32 + i * 16][0], XS_LD);
        #pragma unroll
        for (int j = 0; j < 2; j++)
            wmma::load_matrix_sync(bf[j], &Ws[cur][0][wn * 32 + j * 16], WS_LD);
        #pragma unroll
        for (int i = 0; i < 2; i++)
            #pragma unroll
            for (int j = 0; j < 2; j++)
                wmma::mma_sync(c[i][j], a[i], bf[j], c[i][j]);
    }
    __syncthreads();

    int rhalf = tid >> 4;
    int lane16 = tid & 15;
    #pragma unroll
    for (int p = 0; p < 4; p++) {
        if (wm == (p >> 1)) {
            int i = p & 1;
            wmma::store_matrix_sync(&Epi[0][wn * 32],      c[i][0], EPI_LD, wmma::mem_row_major);
            wmma::store_matrix_sync(&Epi[0][wn * 32 + 16], c[i][1], EPI_LD, wmma::mem_row_major);
        }
        __syncthreads();
        int grow = row0 + p * 16 + rhalf;
        int c0 = lane16 * 8;
        float4 v0 = *(const float4*)&Epi[rhalf][c0];
        float4 v1 = *(const float4*)&Epi[rhalf][c0 + 4];
        uint2 o0 = f4_to_h4(v0);
        uint2 o1 = f4_to_h4(v1);
        *(uint4*)(Yh + (size_t)grow * CCH + c0) = make_uint4(o0.x, o0.y, o1.x, o1.y);
        if (fuse_alar) {
            float al = v0.x * asS[c0]     + v0.y * asS[c0 + 1] + v0.z * asS[c0 + 2] + v0.w * asS[c0 + 3]
                     + v1.x * asS[c0 + 4] + v1.y * asS[c0 + 5] + v1.z * asS[c0 + 6] + v1.w * asS[c0 + 7];
            float ar = v0.x * adS[c0]     + v0.y * adS[c0 + 1] + v0.z * adS[c0 + 2] + v0.w * adS[c0 + 3]
                     + v1.x * adS[c0 + 4] + v1.y * adS[c0 + 5] + v1.z * adS[c0 + 6] + v1.w * adS[c0 + 7];
            #pragma unroll
            for (int off = 8; off; off >>= 1) {
                al += __shfl_down_sync(0xffffffffu, al, off, 16);
                ar += __shfl_down_sync(0xffffffffu, ar, off, 16);
            }
            if (lane16 == 0 && grow < n) { d_al[grow] = al; d_ar[grow] = ar; }
        }
        __syncthreads();
    }
}

// ---------------- GCN aggregation: HALF-WARP per node, uint4 gather, proper masks ---
__global__ __launch_bounds__(256) void gcn_agg_h3(const __half* __restrict__ xwh,
                                                  const float* __restrict__ b,
                                                  float* __restrict__ y, int do_leaky) {
    int node = (blockIdx.x * blockDim.x + threadIdx.x) >> 4;
    int lane = threadIdx.x & 15;
    unsigned hm = 0xffffu << (threadIdx.x & 16);   // mask of THIS half-warp only
    if (node >= N_NODES) return;
    int s = d_row_ptr[node], e = d_row_ptr[node + 1];
    float4 acc0 = make_float4(0.f, 0.f, 0.f, 0.f);
    float4 acc1 = make_float4(0.f, 0.f, 0.f, 0.f);
    const uint4* xw4 = (const uint4*)xwh;   // 8 halves per slot, 16 slots per row
    for (int base = s; base < e; base += 16) {
        int j = base + lane;
        int srcL = 0; float nrmL = 0.f;
        if (j < e) { srcL = d_csr_src[j]; nrmL = d_csr_norm[j]; }
        int cnt = min(16, e - base);
        int q = 0;
        for (; q + 4 <= cnt; q += 4) {
            int s0 = __shfl_sync(hm, srcL, q,     16);
            int s1 = __shfl_sync(hm, srcL, q + 1, 16);
            int s2 = __shfl_sync(hm, srcL, q + 2, 16);
            int s3 = __shfl_sync(hm, srcL, q + 3, 16);
            float n0 = __shfl_sync(hm, nrmL, q,     16);
            float n1 = __shfl_sync(hm, nrmL, q + 1, 16);
            float n2 = __shfl_sync(hm, nrmL, q + 2, 16);
            float n3 = __shfl_sync(hm, nrmL, q + 3, 16);
            uint4 u0 = xw4[(size_t)s0 * 16 + lane];
            uint4 u1 = xw4[(size_t)s1 * 16 + lane];
            uint4 u2 = xw4[(size_t)s2 * 16 + lane];
            uint4 u3 = xw4[(size_t)s3 * 16 + lane];
            fma8(acc0, acc1, u0, n0);
            fma8(acc0, acc1, u1, n1);
            fma8(acc0, acc1, u2, n2);
            fma8(acc0, acc1, u3, n3);
        }
        for (; q < cnt; q++) {
            int   sq = __shfl_sync(hm, srcL, q, 16);
            float nq = __shfl_sync(hm, nrmL, q, 16);
            fma8(acc0, acc1, xw4[(size_t)sq * 16 + lane], nq);
        }
    }
    float4 b0 = ((const float4*)b)[lane * 2];
    float4 b1 = ((const float4*)b)[lane * 2 + 1];
    acc0.x += b0.x; acc0.y += b0.y; acc0.z += b0.z; acc0.w += b0.w;
    acc1.x += b1.x; acc1.y += b1.y; acc1.z += b1.z; acc1.w += b1.w;
    if (do_leaky) {
        acc0.x = leaky01(acc0.x); acc0.y = leaky01(acc0.y);
        acc0.z = leaky01(acc0.z); acc0.w = leaky01(acc0.w);
        acc1.x = leaky01(acc1.x); acc1.y = leaky01(acc1.y);
        acc1.z = leaky01(acc1.z); acc1.w = leaky01(acc1.w);
    }
    float4* yo = (float4*)(y + (size_t)node * CCH);
    yo[lane * 2]     = acc0;
    yo[lane * 2 + 1] = acc1;
}

// ---------------- GAT aggregation: HALF-WARP per node, uint4 gather, proper masks ---
__global__ __launch_bounds__(256) void gat_agg_h3(const __half* __restrict__ xwh,
                                                  const float* __restrict__ b,
                                                  float* __restrict__ y) {
    int node = (blockIdx.x * blockDim.x + threadIdx.x) >> 4;
    int lane = threadIdx.x & 15;
    unsigned hm = 0xffffu << (threadIdx.x & 16);
    if (node >= N_NODES) return;
    int s = d_row_ptr[node], e = d_row_ptr[node + 1];
    float arn = d_ar[node];

    float m = -1e30f;
    for (int j = s + lane; j < e; j += 16)
        m = fmaxf(m, leaky20(d_al[d_csr_src[j]] + arn));
    #pragma unroll
    for (int off = 8; off; off >>= 1) m = fmaxf(m, __shfl_xor_sync(hm, m, off, 16));

    float denom = 0.f;
    float4 acc0 = make_float4(0.f, 0.f, 0.f, 0.f);
    float4 acc1 = make_float4(0.f, 0.f, 0.f, 0.f);
    const uint4* xw4 = (const uint4*)xwh;
    for (int base = s; base < e; base += 16) {
        int j = base + lane;
        int srcL = 0; float exL = 0.f;
        if (j < e) {
            srcL = d_csr_src[j];
            exL = __expf(leaky20(d_al[srcL] + arn) - m);
            denom += exL;
        }
        int cnt = min(16, e - base);
        int q = 0;
        for (; q + 4 <= cnt; q += 4) {
            int s0 = __shfl_sync(hm, srcL, q,     16);
            int s1 = __shfl_sync(hm, srcL, q + 1, 16);
            int s2 = __shfl_sync(hm, srcL, q + 2, 16);
            int s3 = __shfl_sync(hm, srcL, q + 3, 16);
            float a0 = __shfl_sync(hm, exL, q,     16);
            float a1 = __shfl_sync(hm, exL, q + 1, 16);
            float a2 = __shfl_sync(hm, exL, q + 2, 16);
            float a3 = __shfl_sync(hm, exL, q + 3, 16);
            uint4 u0 = xw4[(size_t)s0 * 16 + lane];
            uint4 u1 = xw4[(size_t)s1 * 16 + lane];
            uint4 u2 = xw4[(size_t)s2 * 16 + lane];
            uint4 u3 = xw4[(size_t)s3 * 16 + lane];
            fma8(acc0, acc1, u0, a0);
            fma8(acc0, acc1, u1, a1);
            fma8(acc0, acc1, u2, a2);
            fma8(acc0, acc1, u3, a3);
        }
        for (; q < cnt; q++) {
            int   sq = __shfl_sync(hm, srcL, q, 16);
            float aq = __shfl_sync(hm, exL, q, 16);
            fma8(acc0, acc1, xw4[(size_t)sq * 16 + lane], aq);
        }
    }
    #pragma unroll
    for (int off = 8; off; off >>= 1) denom += __shfl_xor_sync(hm, denom, off, 16);
    float inv = 1.f / denom;

    float4 b0 = ((const float4*)b)[lane * 2];
    float4 b1 = ((const float4*)b)[lane * 2 + 1];
    float4* yo = (float4*)(y + (size_t)node * CCH);
    yo[lane * 2]     = make_float4(acc0.x * inv + b0.x, acc0.y * inv + b0.y,
                                   acc0.z * inv + b0.z, acc0.w * inv + b0.w);
    yo[lane * 2 + 1] = make_float4(acc1.x * inv + b1.x, acc1.y * inv + b1.y,
                                   acc1.z * inv + b1.z, acc1.w * inv + b1.w);
}

// ---------------- GraphNorm stats ----------------
__global__ void norm_reduce(const float* __restrict__ y) {
    int c = threadIdx.x;
    float ls = 0.f, lq = 0.f;
    for (int n = blockIdx.x; n < N_NODES; n += gridDim.x) {
        float v = y[(long)n * CCH + c];
        ls += v; lq += v * v;
    }
    atomicAdd(&d_stat[c], ls);
    atomicAdd(&d_stat[CCH + c], lq);
}

__global__ void norm_final(const float* __restrict__ alpha) {
    int c = threadIdx.x;
    float m = d_stat[c] * (1.0f / N_NODES);
    float q = d_stat[CCH + c] * (1.0f / N_NODES);
    float a = alpha[c];
    float var = q - (2.f * a - a * a) * m * m;
    d_shift[c] = a * m;
    d_rstd[c]  = rsqrtf(var + 1e-5f);
    d_stat[c] = 0.f;
    d_stat[CCH + c] = 0.f;
}

// ---------------- output head ----------------
__global__ void gemv_out_f(const float* __restrict__ x, const float* __restrict__ yin,
                           const float* __restrict__ gamma, const float* __restrict__ beta,
                           const float* __restrict__ Wout) {
    int g = blockIdx.x * blockDim.x + threadIdx.x;
    int node = g >> 5, lane = g & 31;
    if (node >= N_NODES) return;
    float4 xv = ((const float4*)(x + (size_t)node * CCH))[lane];
    float4 yv = ((const float4*)(yin + (size_t)node * CCH))[lane];
    float4 gm = ((const float4*)gamma)[lane];
    float4 bt = ((const float4*)beta)[lane];
    float4 sh = ((const float4*)d_shift)[lane];
    float4 rs = ((const float4*)d_rstd)[lane];
    float4 w  = ((const float4*)Wout)[lane];
    float vx = xv.x + leaky01(gm.x * (yv.x - sh.x) * rs.x + bt.x);
    float vy = xv.y + leaky01(gm.y * (yv.y - sh.y) * rs.y + bt.y);
    float vz = xv.z + leaky01(gm.z * (yv.z - sh.z) * rs.z + bt.z);
    float vw = xv.w + leaky01(gm.w * (yv.w - sh.w) * rs.w + bt.w);
    float d = vx * w.x + vy * w.y + vz * w.z + vw * w.w;
    #pragma unroll
    for (int off = 16; off; off >>= 1) d += __shfl_down_sync(0xffffffffu, d, off);
    if (lane == 0) d_xw1[node] = d;
}

__global__ void scalar_agg(const float* __restrict__ b_out) {
    int g = blockIdx.x * blockDim.x + threadIdx.x;
    int node = g >> 5, lane = g & 31;
    if (node >= N_NODES) return;
    int s = d_row_ptr[node], e = d_row_ptr[node + 1];
    float acc = 0.f;
    for (int j = s + lane; j < e; j += 32)
        acc += d_csr_norm[j] * d_xw1[d_csr_src[j]];
    #pragma unroll
    for (int off = 16; off; off >>= 1) acc += __shfl_down_sync(0xffffffffu, acc, off);
    if (lane == 0) d_xs[node] = leaky01(acc + b_out[0]);
}

__global__ void fc1_partial(const float* __restrict__ W1) {
    int c = threadIdx.x;
    float acc = 0.f;
    for (int n = blockIdx.x; n < N_NODES; n += gridDim.x)
        acc += d_xs[n] * W1[(long)n * CCH + c];
    atomicAdd(&d_hraw[c], acc);
}

__global__ void fc1_final(const float* __restrict__ b1) {
    int c = threadIdx.x;
    float v = d_hraw[c] + b1[c];
    d_h[c] = v > 0.f ? v : 0.f;
}

__global__ void fc2_k(const float* __restrict__ W2, const float* __restrict__ b2,
                      float* __restrict__ out) {
    __shared__ float hs[CCH];
    int tid = threadIdx.x;
    hs[tid] = d_h[tid];
    __syncthreads();
    int p = blockIdx.x * 128 + tid;
    if (p >= POI_LEN_) return;
    float acc = b2[p];
    #pragma unroll 8
    for (int j = 0; j < CCH; j++)
        acc += hs[j] * W2[(long)j * POI_LEN_ + p];
    out[p] = acc > 0.f ? acc : 0.f;
}

// ---------------- launch ----------------
static inline int div_up(int a, int b) { return (a + b - 1) / b; }

extern "C" void kernel_launch(void* const* d_in, const int* in_sizes, int n_in,
                              void* d_out, int out_size) {
    const int*   poi_ids   = (const int*)  d_in[0];
    const int*   cat_ids   = (const int*)  d_in[1];
    const float* feat3     = (const float*)d_in[2];
    const int*   edge_index= (const int*)  d_in[3];
    const float* edge_w    = (const float*)d_in[4];
    const float* poi_emb   = (const float*)d_in[5];
    const float* cat_emb   = (const float*)d_in[6];
    const float* Win       = (const float*)d_in[7];
    const float* b_in      = (const float*)d_in[8];
    const float* gcn_W     = (const float*)d_in[9];
    const float* gcn_b     = (const float*)d_in[10];
    const float* gn_gamma  = (const float*)d_in[11];
    const float* gn_beta   = (const float*)d_in[12];
    const float* gn_alpha  = (const float*)d_in[13];
    const float* gat_W     = (const float*)d_in[14];
    const float* gat_asrc  = (const float*)d_in[15];
    const float* gat_adst  = (const float*)d_in[16];
    const float* gat_b     = (const float*)d_in[17];
    const float* Wout      = (const float*)d_in[18];
    const float* b_out     = (const float*)d_in[19];
    const float* fc_W1     = (const float*)d_in[20];
    const float* fc_b1     = (const float*)d_in[21];
    const float* fc_W2     = (const float*)d_in[22];
    const float* fc_b2     = (const float*)d_in[23];
    float* out = (float*)d_out;

    float *feat_p, *x_p, *y_p; __half *xwh_p;
    cudaGetSymbolAddress((void**)&feat_p, d_feat);
    cudaGetSymbolAddress((void**)&x_p,  d_x);
    cudaGetSymbolAddress((void**)&y_p,  d_y);
    cudaGetSymbolAddress((void**)&xwh_p, d_xwh);

    const int warpGrid = div_up(N_NODES * 32, 256);
    const int edgeGrid = div_up(NEDGES, 256);
    const int gemmGrid = N_PAD / GM;               // 600
    const int aggGrid  = div_up(N_NODES, 16);      // 16 nodes per 256-thread block

    feat_k<<<N_NODES, 128>>>(poi_ids, cat_ids, feat3, poi_emb, cat_emb);
    init_k<<<div_up(N_NODES, 256), 256>>>();
    hist_k<<<edgeGrid, 256>>>(edge_index);
    gemm_h16_db<<<gemmGrid, 256>>>(feat_p, Win, xwh_p, N_NODES, FEAT_DIM,
                                   nullptr, nullptr, nullptr, nullptr, 0,
                                   nullptr, nullptr, 0);
    scan_k<<<1, 1024>>>();
    selfloop_k<<<div_up(N_NODES, 256), 256>>>();
    scatter_k<<<edgeGrid, 256>>>(edge_index, edge_w);
    deg_k<<<warpGrid, 256>>>();
    csnorm_k<<<warpGrid, 256>>>();

    gcn_agg_h3<<<aggGrid, 256>>>(xwh_p, b_in, x_p, 1);

    for (int l = 0; l < NLAYERS; l++) {
        // GCN half: gemm (prev GAT norm fused for l>0)
        if (l == 0)
            gemm_h16_db<<<gemmGrid, 256>>>(x_p, gcn_W, xwh_p, N_NODES, CCH,
                                           nullptr, nullptr, nullptr, nullptr, 0,
                                           nullptr, nullptr, 0);
        else
            gemm_h16_db<<<gemmGrid, 256>>>(nullptr, gcn_W + l * CCH * CCH, xwh_p, N_NODES, CCH,
                                           y_p, x_p,
                                           gn_gamma + (l - 1) * CCH, gn_beta + (l - 1) * CCH, 1,
                                           nullptr, nullptr, 0);
        gcn_agg_h3<<<aggGrid, 256>>>(xwh_p, gcn_b + l * CCH, y_p, 0);
        norm_reduce<<<592, 128>>>(y_p);
        norm_final<<<1, 128>>>(gn_alpha + l * CCH);

        // GAT half: gemm with fused GCN norm + alar epilogue
        gemm_h16_db<<<gemmGrid, 256>>>(nullptr, gat_W + l * CCH * CCH, xwh_p, N_NODES, CCH,
                                       y_p, x_p,
                                       gn_gamma + l * CCH, gn_beta + l * CCH, 1,
                                       gat_asrc + l * CCH, gat_adst + l * CCH, 1);
        gat_agg_h3<<<aggGrid, 256>>>(xwh_p, gat_b + l * CCH, y_p);
        norm_reduce<<<592, 128>>>(y_p);
        norm_final<<<1, 128>>>(gn_alpha + l * CCH);
    }

    // output conv (final norm fused) + FC head
    gemv_out_f<<<warpGrid, 256>>>(x_p, y_p, gn_gamma + 4 * CCH, gn_beta + 4 * CCH, Wout);
    scalar_agg<<<warpGrid, 256>>>(b_out);
    fc1_partial<<<592, 128>>>(fc_W1);
    fc1_final<<<1, 128>>>(fc_b1);
    fc2_k<<<div_up(POI_LEN_, 128), 128>>>(fc_W2, fc_b2, out);
}

// round 15
// speedup vs baseline: 1.0152x; 1.0152x over previous
#include <cuda_runtime.h>
#include <cuda_fp16.h>
#include <mma.h>
#include <math.h>

using namespace nvcuda;

#define N_NODES 38332
#define N_PAD   38400
#define POI_LEN_ 38333
#define POI_DIM 300
#define CAT_DIM 100
#define FEAT_DIM 403
#define FD_PAD  416          /* feat width padded to multiple of 16 */
#define CCH 128
#define NLAYERS 5
#define NEDGES 1200000
#define TOTE (NEDGES + N_NODES)
#define NEG 0.01f
#define GAT_NEG 0.2f
#define FULLM 0xffffffffu

// ---------------- scratch (static __device__, no allocation) ----------------
__device__ __half d_feath[N_NODES * FD_PAD];
__device__ float  d_x [N_NODES * CCH];
__device__ __half d_xwh[N_PAD * CCH];
__device__ float  d_y [N_NODES * CCH];
__device__ int    d_csr_src [TOTE];
__device__ float  d_csr_w   [TOTE];
__device__ float  d_csr_norm[TOTE];
__device__ int    d_row_ptr[N_NODES + 1];
__device__ int    d_cnt   [N_NODES];
__device__ int    d_cursor[N_NODES];
__device__ float  d_dinv[N_NODES];
__device__ float  d_al [N_NODES];
__device__ float  d_ar [N_NODES];
__device__ float  d_xw1[N_NODES];
__device__ float  d_xs [N_NODES];
__device__ float  d_stat[2 * CCH];
__device__ float  d_shift[CCH];
__device__ float  d_rstd [CCH];
__device__ float  d_hraw[CCH];
__device__ float  d_h   [CCH];

__device__ __forceinline__ float leaky01(float v) { return v > 0.f ? v : NEG * v; }
__device__ __forceinline__ float leaky20(float v) { return v > 0.f ? v : GAT_NEG * v; }

__device__ __forceinline__ float4 h4_to_f4(uint2 u) {
    float4 r;
    asm("{\n\t"
        ".reg .b16 a, b, c, d;\n\t"
        "mov.b32 {a, b}, %4;\n\t"
        "mov.b32 {c, d}, %5;\n\t"
        "cvt.f32.f16 %0, a;\n\t"
        "cvt.f32.f16 %1, b;\n\t"
        "cvt.f32.f16 %2, c;\n\t"
        "cvt.f32.f16 %3, d;\n\t"
        "}"
        : "=f"(r.x), "=f"(r.y), "=f"(r.z), "=f"(r.w)
        : "r"(u.x), "r"(u.y));
    return r;
}

__device__ __forceinline__ uint2 f4_to_h4(float4 v) {
    __half2 h0 = __floats2half2_rn(v.x, v.y);
    __half2 h1 = __floats2half2_rn(v.z, v.w);
    return make_uint2(*(unsigned*)&h0, *(unsigned*)&h1);
}

__device__ __forceinline__ void fma8(float4& a0, float4& a1, uint4 u, float w) {
    float4 v0 = h4_to_f4(make_uint2(u.x, u.y));
    a0.x += w * v0.x; a0.y += w * v0.y; a0.z += w * v0.z; a0.w += w * v0.w;
    float4 v1 = h4_to_f4(make_uint2(u.z, u.w));
    a1.x += w * v1.x; a1.y += w * v1.y; a1.z += w * v1.z; a1.w += w * v1.w;
}

// ---------------- CSR build ----------------
__global__ void init_k() {
    int i = blockIdx.x * blockDim.x + threadIdx.x;
    if (i < N_NODES) d_cnt[i] = 1;
    if (i < CCH)     d_hraw[i] = 0.f;
    if (i < 2 * CCH) d_stat[i] = 0.f;
}

__global__ void hist_k(const int* __restrict__ ei) {
    int e = blockIdx.x * blockDim.x + threadIdx.x;
    if (e < NEDGES) atomicAdd(&d_cnt[ei[NEDGES + e]], 1);
}

__global__ void scan_k() {
    const int T = 1024;
    const int ITEMS = (N_NODES + T - 1) / T;
    int tid = threadIdx.x;
    int start = tid * ITEMS;
    int end   = min(start + ITEMS, N_NODES);
    int s = 0;
    for (int i = start; i < end; i++) s += d_cnt[i];
    __shared__ int ps[T];
    ps[tid] = s; __syncthreads();
    for (int off = 1; off < T; off <<= 1) {
        int v = (tid >= off) ? ps[tid - off] : 0;
        __syncthreads();
        ps[tid] += v;
        __syncthreads();
    }
    int incl = ps[tid];
    int run  = incl - s;
    for (int i = start; i < end; i++) { d_row_ptr[i] = run; run += d_cnt[i]; }
    if (tid == T - 1) d_row_ptr[N_NODES] = incl;
}

__global__ void selfloop_k() {
    int i = blockIdx.x * blockDim.x + threadIdx.x;
    if (i < N_NODES) {
        int p = d_row_ptr[i];
        d_csr_src[p] = i;
        d_csr_w[p]   = 1.0f;
        d_cursor[i]  = p + 1;
    }
}

__global__ void scatter_k(const int* __restrict__ ei, const float* __restrict__ ew) {
    int e = blockIdx.x * blockDim.x + threadIdx.x;
    if (e < NEDGES) {
        int dst = ei[NEDGES + e];
        int p = atomicAdd(&d_cursor[dst], 1);
        d_csr_src[p] = ei[e];
        d_csr_w[p]   = ew[e];
    }
}

__global__ void deg_k() {
    int g = blockIdx.x * blockDim.x + threadIdx.x;
    int node = g >> 5, lane = g & 31;
    if (node >= N_NODES) return;
    int s = d_row_ptr[node], e = d_row_ptr[node + 1];
    float acc = 0.f;
    for (int j = s + lane; j < e; j += 32) acc += d_csr_w[j];
    #pragma unroll
    for (int off = 16; off; off >>= 1) acc += __shfl_down_sync(FULLM, acc, off);
    if (lane == 0) d_dinv[node] = rsqrtf(acc);
}

__global__ void csnorm_k() {
    int g = blockIdx.x * blockDim.x + threadIdx.x;
    int node = g >> 5, lane = g & 31;
    if (node >= N_NODES) return;
    int s = d_row_ptr[node], e = d_row_ptr[node + 1];
    float dv = d_dinv[node];
    for (int j = s + lane; j < e; j += 32)
        d_csr_norm[j] = d_dinv[d_csr_src[j]] * d_csr_w[j] * dv;
}

// ---------------- feature assembly (fp16, padded) ----------------
__global__ void feat_k(const int* __restrict__ poi_ids, const int* __restrict__ cat_ids,
                       const float* __restrict__ feat3,
                       const float* __restrict__ poi_emb, const float* __restrict__ cat_emb) {
    int node = blockIdx.x, tid = threadIdx.x;
    int pid = poi_ids[node], cid = cat_ids[node];
    __half* f = d_feath + (size_t)node * FD_PAD;
    for (int k = tid; k < POI_DIM; k += 128) f[k] = __float2half_rn(poi_emb[(size_t)pid * POI_DIM + k]);
    for (int k = tid; k < CAT_DIM; k += 128) f[POI_DIM + k] = __float2half_rn(cat_emb[cid * CAT_DIM + k]);
    if (tid < 3)  f[400 + tid] = __float2half_rn(feat3[node * 3 + tid]);
    if (tid >= 3 && tid < 16) f[400 + tid] = __float2half_rn(0.f);   // pad 403..415
}

// ---------------- GEMM (fp16 HMMA, double-buffered, fused norm loader) --------------
#define GM 64
#define GN 128
#define GK 16
#define XS_LD 24
#define WS_LD 136
#define EPI_LD 132

#define XS_BYTES (2 * GM * XS_LD * 2)
#define WS_BYTES (2 * GK * WS_LD * 2)
#define SMEM_BYTES (XS_BYTES + WS_BYTES)

__global__ __launch_bounds__(256) void gemm_h16_db(
    const float* __restrict__ X, const __half* __restrict__ Xh,
    const float* __restrict__ W, __half* __restrict__ Yh,
    int n, int K, int Kw,
    const float* __restrict__ yin, float* __restrict__ xio,
    const float* __restrict__ gamma, const float* __restrict__ beta, int fuse_norm,
    const float* __restrict__ asrc, const float* __restrict__ adst, int fuse_alar) {
    __shared__ __align__(16) char smem_raw[SMEM_BYTES];
    typedef __half XsRow[GM][XS_LD];
    typedef __half WsRow[GK][WS_LD];
    XsRow* Xs = reinterpret_cast<XsRow*>(smem_raw);
    WsRow* Ws = reinterpret_cast<WsRow*>(smem_raw + XS_BYTES);
    float (*Epi)[EPI_LD] = reinterpret_cast<float (*)[EPI_LD]>(smem_raw);
    __shared__ float asS[CCH], adS[CCH];
    __shared__ float gS[CCH], bS[CCH], shS[CCH], rsS[CCH];

    int tid = threadIdx.x;
    int warp = tid >> 5;
    int wm = warp & 1;
    int wn = warp >> 1;
    int row0 = blockIdx.x * GM;

    if (fuse_alar && tid < CCH) { asS[tid] = asrc[tid]; adS[tid] = adst[tid]; }
    if (fuse_norm) {
        if (tid < CCH) {
            gS[tid] = gamma[tid]; bS[tid] = beta[tid];
            shS[tid] = d_shift[tid]; rsS[tid] = d_rstd[tid];
        }
        __syncthreads();
    }

    wmma::fragment<wmma::accumulator, 16, 16, 16, float> c[2][2];
    #pragma unroll
    for (int i = 0; i < 2; i++)
        #pragma unroll
        for (int j = 0; j < 2; j++) wmma::fill_fragment(c[i][j], 0.f);

    int nIter = (K + GK - 1) / GK;

    int rX = tid >> 2;
    int kX = (tid & 3) * 4;
    int gr = row0 + rX;
    uint2 xr; uint2 wr[2];

    auto loadX = [&](int gk0) -> uint2 {
        if (fuse_norm) {
            if (gr < n) {
                size_t off = (size_t)gr * CCH + gk0;
                float4 yv = *(const float4*)(yin + off);
                float4 xv = *(const float4*)(xio + off);
                float4 v;
                v.x = xv.x + leaky01(gS[gk0]     * (yv.x - shS[gk0])     * rsS[gk0]     + bS[gk0]);
                v.y = xv.y + leaky01(gS[gk0 + 1] * (yv.y - shS[gk0 + 1]) * rsS[gk0 + 1] + bS[gk0 + 1]);
                v.z = xv.z + leaky01(gS[gk0 + 2] * (yv.z - shS[gk0 + 2]) * rsS[gk0 + 2] + bS[gk0 + 2]);
                v.w = xv.w + leaky01(gS[gk0 + 3] * (yv.w - shS[gk0 + 3]) * rsS[gk0 + 3] + bS[gk0 + 3]);
                *(float4*)(xio + off) = v;
                return f4_to_h4(v);
            }
            return make_uint2(0u, 0u);
        }
        if (Xh) {                       // fp16 input, K padded -> unguarded col access
            if (gr < n) return *(const uint2*)(Xh + (size_t)gr * K + gk0);
            return make_uint2(0u, 0u);
        }
        float xv[4];
        #pragma unroll
        for (int t = 0; t < 4; t++) {
            int gk = gk0 + t;
            xv[t] = (gr < n && gk < K) ? X[(size_t)gr * K + gk] : 0.f;
        }
        return f4_to_h4(make_float4(xv[0], xv[1], xv[2], xv[3]));
    };

    xr = loadX(kX);
    #pragma unroll
    for (int i = 0; i < 2; i++) {
        int e = (tid + i * 256) * 4;
        int rW = e >> 7, cW = e & 127;
        float4 v = (rW < Kw) ? *(const float4*)(W + (size_t)rW * GN + cW)
                             : make_float4(0.f, 0.f, 0.f, 0.f);
        wr[i] = f4_to_h4(v);
    }

    for (int it = 0; it < nIter; it++) {
        int cur = it & 1;
        *(uint2*)&Xs[cur][rX][kX] = xr;
        #pragma unroll
        for (int i = 0; i < 2; i++) {
            int e = (tid + i * 256) * 4;
            int rW = e >> 7, cW = e & 127;
            *(uint2*)&Ws[cur][rW][cW] = wr[i];
        }
        __syncthreads();
        if (it + 1 < nIter) {
            int k0 = (it + 1) * GK;
            xr = loadX(k0 + kX);
            #pragma unroll
            for (int i = 0; i < 2; i++) {
                int e = (tid + i * 256) * 4;
                int rW = e >> 7, cW = e & 127;
                int gk = k0 + rW;
                float4 v = (gk < Kw) ? *(const float4*)(W + (size_t)gk * GN + cW)
                                     : make_float4(0.f, 0.f, 0.f, 0.f);
                wr[i] = f4_to_h4(v);
            }
        }
        wmma::fragment<wmma::matrix_a, 16, 16, 16, __half, wmma::row_major> a[2];
        wmma::fragment<wmma::matrix_b, 16, 16, 16, __half, wmma::row_major> bf[2];
        #pragma unroll
        for (int i = 0; i < 2; i++)
            wmma::load_matrix_sync(a[i], &Xs[cur][wm * 32 + i * 16][0], XS_LD);
        #pragma unroll
        for (int j = 0; j < 2; j++)
            wmma::load_matrix_sync(bf[j], &Ws[cur][0][wn * 32 + j * 16], WS_LD);
        #pragma unroll
        for (int i = 0; i < 2; i++)
            #pragma unroll
            for (int j = 0; j < 2; j++)
                wmma::mma_sync(c[i][j], a[i], bf[j], c[i][j]);
    }
    __syncthreads();

    int rhalf = tid >> 4;
    int lane16 = tid & 15;
    #pragma unroll
    for (int p = 0; p < 4; p++) {
        if (wm == (p >> 1)) {
            int i = p & 1;
            wmma::store_matrix_sync(&Epi[0][wn * 32],      c[i][0], EPI_LD, wmma::mem_row_major);
            wmma::store_matrix_sync(&Epi[0][wn * 32 + 16], c[i][1], EPI_LD, wmma::mem_row_major);
        }
        __syncthreads();
        int grow = row0 + p * 16 + rhalf;
        int c0 = lane16 * 8;
        float4 v0 = *(const float4*)&Epi[rhalf][c0];
        float4 v1 = *(const float4*)&Epi[rhalf][c0 + 4];
        uint2 o0 = f4_to_h4(v0);
        uint2 o1 = f4_to_h4(v1);
        *(uint4*)(Yh + (size_t)grow * CCH + c0) = make_uint4(o0.x, o0.y, o1.x, o1.y);
        if (fuse_alar) {
            float al = v0.x * asS[c0]     + v0.y * asS[c0 + 1] + v0.z * asS[c0 + 2] + v0.w * asS[c0 + 3]
                     + v1.x * asS[c0 + 4] + v1.y * asS[c0 + 5] + v1.z * asS[c0 + 6] + v1.w * asS[c0 + 7];
            float ar = v0.x * adS[c0]     + v0.y * adS[c0 + 1] + v0.z * adS[c0 + 2] + v0.w * adS[c0 + 3]
                     + v1.x * adS[c0 + 4] + v1.y * adS[c0 + 5] + v1.z * adS[c0 + 6] + v1.w * adS[c0 + 7];
            #pragma unroll
            for (int off = 8; off; off >>= 1) {
                al += __shfl_down_sync(FULLM, al, off, 16);
                ar += __shfl_down_sync(FULLM, ar, off, 16);
            }
            if (lane16 == 0 && grow < n) { d_al[grow] = al; d_ar[grow] = ar; }
        }
        __syncthreads();
    }
}

// ---- GCN aggregation: WARP per node, paired edges (uint4 per half-warp) -----------
__global__ __launch_bounds__(256) void gcn_agg_h4(const __half* __restrict__ xwh,
                                                  const float* __restrict__ b,
                                                  float* __restrict__ y, int do_leaky) {
    int node = (blockIdx.x * blockDim.x + threadIdx.x) >> 5;
    int lane = threadIdx.x & 31;
    int half = lane >> 4;            // edge parity handled by this lane
    int l16  = lane & 15;            // channel slot (8 ch per slot)
    if (node >= N_NODES) return;
    int s = d_row_ptr[node], e = d_row_ptr[node + 1];
    float4 a0 = make_float4(0.f, 0.f, 0.f, 0.f);
    float4 a1 = make_float4(0.f, 0.f, 0.f, 0.f);
    const uint4* xw4 = (const uint4*)xwh;
    for (int base = s; base < e; base += 32) {
        int j = base + lane;
        int srcL = 0; float nrmL = 0.f;
        if (j < e) { srcL = d_csr_src[j]; nrmL = d_csr_norm[j]; }
        int cnt = min(32, e - base);
        int q = 0;
        for (; q + 8 <= cnt; q += 8) {     // 4 edge-pairs
            int   sq[4]; float wq[4]; uint4 uq[4];
            #pragma unroll
            for (int t = 0; t < 4; t++) {
                int qq = q + 2 * t + half;
                sq[t] = __shfl_sync(FULLM, srcL, qq);
                wq[t] = __shfl_sync(FULLM, nrmL, qq);
            }
            #pragma unroll
            for (int t = 0; t < 4; t++) uq[t] = xw4[(size_t)sq[t] * 16 + l16];
            #pragma unroll
            for (int t = 0; t < 4; t++) fma8(a0, a1, uq[t], wq[t]);
        }
        for (; q < cnt; q += 2) {
            int qq = q + half;             // lane index <= cnt <= 31; zero weight if beyond
            int   sq = __shfl_sync(FULLM, srcL, qq);
            float wq = __shfl_sync(FULLM, nrmL, qq);
            fma8(a0, a1, xw4[(size_t)sq * 16 + l16], wq);
        }
    }
    // merge even/odd-edge partials across half-warps
    #pragma unroll
    for (int k = 0; k < 1; k++) {}  // (no-op; keep structure flat)
    a0.x += __shfl_xor_sync(FULLM, a0.x, 16); a0.y += __shfl_xor_sync(FULLM, a0.y, 16);
    a0.z += __shfl_xor_sync(FULLM, a0.z, 16); a0.w += __shfl_xor_sync(FULLM, a0.w, 16);
    a1.x += __shfl_xor_sync(FULLM, a1.x, 16); a1.y += __shfl_xor_sync(FULLM, a1.y, 16);
    a1.z += __shfl_xor_sync(FULLM, a1.z, 16); a1.w += __shfl_xor_sync(FULLM, a1.w, 16);
    if (half == 0) {
        float4 b0 = ((const float4*)b)[l16 * 2];
        float4 b1 = ((const float4*)b)[l16 * 2 + 1];
        a0.x += b0.x; a0.y += b0.y; a0.z += b0.z; a0.w += b0.w;
        a1.x += b1.x; a1.y += b1.y; a1.z += b1.z; a1.w += b1.w;
        if (do_leaky) {
            a0.x = leaky01(a0.x); a0.y = leaky01(a0.y); a0.z = leaky01(a0.z); a0.w = leaky01(a0.w);
            a1.x = leaky01(a1.x); a1.y = leaky01(a1.y); a1.z = leaky01(a1.z); a1.w = leaky01(a1.w);
        }
        float4* yo = (float4*)(y + (size_t)node * CCH);
        yo[l16 * 2]     = a0;
        yo[l16 * 2 + 1] = a1;
    }
}

// ---- GAT aggregation: WARP per node, paired edges ----------------------------------
__global__ __launch_bounds__(256) void gat_agg_h4(const __half* __restrict__ xwh,
                                                  const float* __restrict__ b,
                                                  float* __restrict__ y) {
    int node = (blockIdx.x * blockDim.x + threadIdx.x) >> 5;
    int lane = threadIdx.x & 31;
    int half = lane >> 4;
    int l16  = lane & 15;
    if (node >= N_NODES) return;
    int s = d_row_ptr[node], e = d_row_ptr[node + 1];
    float arn = d_ar[node];

    float m = -1e30f;
    for (int j = s + lane; j < e; j += 32)
        m = fmaxf(m, leaky20(d_al[d_csr_src[j]] + arn));
    #pragma unroll
    for (int off = 16; off; off >>= 1) m = fmaxf(m, __shfl_xor_sync(FULLM, m, off));

    float denom = 0.f;
    float4 a0 = make_float4(0.f, 0.f, 0.f, 0.f);
    float4 a1 = make_float4(0.f, 0.f, 0.f, 0.f);
    const uint4* xw4 = (const uint4*)xwh;
    for (int base = s; base < e; base += 32) {
        int j = base + lane;
        int srcL = 0; float exL = 0.f;
        if (j < e) {
            srcL = d_csr_src[j];
            exL = __expf(leaky20(d_al[srcL] + arn) - m);
            denom += exL;
        }
        int cnt = min(32, e - base);
        int q = 0;
        for (; q + 8 <= cnt; q += 8) {
            int   sq[4]; float wq[4]; uint4 uq[4];
            #pragma unroll
            for (int t = 0; t < 4; t++) {
                int qq = q + 2 * t + half;
                sq[t] = __shfl_sync(FULLM, srcL, qq);
                wq[t] = __shfl_sync(FULLM, exL, qq);
            }
            #pragma unroll
            for (int t = 0; t < 4; t++) uq[t] = xw4[(size_t)sq[t] * 16 + l16];
            #pragma unroll
            for (int t = 0; t < 4; t++) fma8(a0, a1, uq[t], wq[t]);
        }
        for (; q < cnt; q += 2) {
            int qq = q + half;
            int   sq = __shfl_sync(FULLM, srcL, qq);
            float wq = __shfl_sync(FULLM, exL, qq);
            fma8(a0, a1, xw4[(size_t)sq * 16 + l16], wq);
        }
    }
    #pragma unroll
    for (int off = 16; off; off >>= 1) denom += __shfl_xor_sync(FULLM, denom, off);
    float inv = 1.f / denom;

    a0.x += __shfl_xor_sync(FULLM, a0.x, 16); a0.y += __shfl_xor_sync(FULLM, a0.y, 16);
    a0.z += __shfl_xor_sync(FULLM, a0.z, 16); a0.w += __shfl_xor_sync(FULLM, a0.w, 16);
    a1.x += __shfl_xor_sync(FULLM, a1.x, 16); a1.y += __shfl_xor_sync(FULLM, a1.y, 16);
    a1.z += __shfl_xor_sync(FULLM, a1.z, 16); a1.w += __shfl_xor_sync(FULLM, a1.w, 16);
    if (half == 0) {
        float4 b0 = ((const float4*)b)[l16 * 2];
        float4 b1 = ((const float4*)b)[l16 * 2 + 1];
        float4* yo = (float4*)(y + (size_t)node * CCH);
        yo[l16 * 2]     = make_float4(a0.x * inv + b0.x, a0.y * inv + b0.y,
                                      a0.z * inv + b0.z, a0.w * inv + b0.w);
        yo[l16 * 2 + 1] = make_float4(a1.x * inv + b1.x, a1.y * inv + b1.y,
                                      a1.z * inv + b1.z, a1.w * inv + b1.w);
    }
}

// ---------------- GraphNorm stats ----------------
__global__ void norm_reduce(const float* __restrict__ y) {
    int c = threadIdx.x;
    float ls = 0.f, lq = 0.f;
    for (int n = blockIdx.x; n < N_NODES; n += gridDim.x) {
        float v = y[(long)n * CCH + c];
        ls += v; lq += v * v;
    }
    atomicAdd(&d_stat[c], ls);
    atomicAdd(&d_stat[CCH + c], lq);
}

__global__ void norm_final(const float* __restrict__ alpha) {
    int c = threadIdx.x;
    float m = d_stat[c] * (1.0f / N_NODES);
    float q = d_stat[CCH + c] * (1.0f / N_NODES);
    float a = alpha[c];
    float var = q - (2.f * a - a * a) * m * m;
    d_shift[c] = a * m;
    d_rstd[c]  = rsqrtf(var + 1e-5f);
    d_stat[c] = 0.f;
    d_stat[CCH + c] = 0.f;
}

// ---------------- output head ----------------
__global__ void gemv_out_f(const float* __restrict__ x, const float* __restrict__ yin,
                           const float* __restrict__ gamma, const float* __restrict__ beta,
                           const float* __restrict__ Wout) {
    int g = blockIdx.x * blockDim.x + threadIdx.x;
    int node = g >> 5, lane = g & 31;
    if (node >= N_NODES) return;
    float4 xv = ((const float4*)(x + (size_t)node * CCH))[lane];
    float4 yv = ((const float4*)(yin + (size_t)node * CCH))[lane];
    float4 gm = ((const float4*)gamma)[lane];
    float4 bt = ((const float4*)beta)[lane];
    float4 sh = ((const float4*)d_shift)[lane];
    float4 rs = ((const float4*)d_rstd)[lane];
    float4 w  = ((const float4*)Wout)[lane];
    float vx = xv.x + leaky01(gm.x * (yv.x - sh.x) * rs.x + bt.x);
    float vy = xv.y + leaky01(gm.y * (yv.y - sh.y) * rs.y + bt.y);
    float vz = xv.z + leaky01(gm.z * (yv.z - sh.z) * rs.z + bt.z);
    float vw = xv.w + leaky01(gm.w * (yv.w - sh.w) * rs.w + bt.w);
    float d = vx * w.x + vy * w.y + vz * w.z + vw * w.w;
    #pragma unroll
    for (int off = 16; off; off >>= 1) d += __shfl_down_sync(FULLM, d, off);
    if (lane == 0) d_xw1[node] = d;
}

__global__ void scalar_agg(const float* __restrict__ b_out) {
    int g = blockIdx.x * blockDim.x + threadIdx.x;
    int node = g >> 5, lane = g & 31;
    if (node >= N_NODES) return;
    int s = d_row_ptr[node], e = d_row_ptr[node + 1];
    float acc = 0.f;
    for (int j = s + lane; j < e; j += 32)
        acc += d_csr_norm[j] * d_xw1[d_csr_src[j]];
    #pragma unroll
    for (int off = 16; off; off >>= 1) acc += __shfl_down_sync(FULLM, acc, off);
    if (lane == 0) d_xs[node] = leaky01(acc + b_out[0]);
}

__global__ void fc1_partial(const float* __restrict__ W1) {
    int c = threadIdx.x;
    float acc = 0.f;
    for (int n = blockIdx.x; n < N_NODES; n += gridDim.x)
        acc += d_xs[n] * W1[(long)n * CCH + c];
    atomicAdd(&d_hraw[c], acc);
}

__global__ void fc1_final(const float* __restrict__ b1) {
    int c = threadIdx.x;
    float v = d_hraw[c] + b1[c];
    d_h[c] = v > 0.f ? v : 0.f;
}

__global__ void fc2_k(const float* __restrict__ W2, const float* __restrict__ b2,
                      float* __restrict__ out) {
    __shared__ float hs[CCH];
    int tid = threadIdx.x;
    hs[tid] = d_h[tid];
    __syncthreads();
    int p = blockIdx.x * 128 + tid;
    if (p >= POI_LEN_) return;
    float acc = b2[p];
    #pragma unroll 8
    for (int j = 0; j < CCH; j++)
        acc += hs[j] * W2[(long)j * POI_LEN_ + p];
    out[p] = acc > 0.f ? acc : 0.f;
}

// ---------------- launch ----------------
static inline int div_up(int a, int b) { return (a + b - 1) / b; }

extern "C" void kernel_launch(void* const* d_in, const int* in_sizes, int n_in,
                              void* d_out, int out_size) {
    const int*   poi_ids   = (const int*)  d_in[0];
    const int*   cat_ids   = (const int*)  d_in[1];
    const float* feat3     = (const float*)d_in[2];
    const int*   edge_index= (const int*)  d_in[3];
    const float* edge_w    = (const float*)d_in[4];
    const float* poi_emb   = (const float*)d_in[5];
    const float* cat_emb   = (const float*)d_in[6];
    const float* Win       = (const float*)d_in[7];
    const float* b_in      = (const float*)d_in[8];
    const float* gcn_W     = (const float*)d_in[9];
    const float* gcn_b     = (const float*)d_in[10];
    const float* gn_gamma  = (const float*)d_in[11];
    const float* gn_beta   = (const float*)d_in[12];
    const float* gn_alpha  = (const float*)d_in[13];
    const float* gat_W     = (const float*)d_in[14];
    const float* gat_asrc  = (const float*)d_in[15];
    const float* gat_adst  = (const float*)d_in[16];
    const float* gat_b     = (const float*)d_in[17];
    const float* Wout      = (const float*)d_in[18];
    const float* b_out     = (const float*)d_in[19];
    const float* fc_W1     = (const float*)d_in[20];
    const float* fc_b1     = (const float*)d_in[21];
    const float* fc_W2     = (const float*)d_in[22];
    const float* fc_b2     = (const float*)d_in[23];
    float* out = (float*)d_out;

    float *x_p, *y_p; __half *xwh_p, *feath_p;
    cudaGetSymbolAddress((void**)&x_p,  d_x);
    cudaGetSymbolAddress((void**)&y_p,  d_y);
    cudaGetSymbolAddress((void**)&xwh_p, d_xwh);
    cudaGetSymbolAddress((void**)&feath_p, d_feath);

    const int warpGrid = div_up(N_NODES * 32, 256);
    const int edgeGrid = div_up(NEDGES, 256);
    const int gemmGrid = N_PAD / GM;               // 600
    const int aggGrid  = div_up(N_NODES, 8);       // warp per node

    feat_k<<<N_NODES, 128>>>(poi_ids, cat_ids, feat3, poi_emb, cat_emb);
    init_k<<<div_up(N_NODES, 256), 256>>>();
    hist_k<<<edgeGrid, 256>>>(edge_index);
    gemm_h16_db<<<gemmGrid, 256>>>(nullptr, feath_p, Win, xwh_p, N_NODES, FD_PAD, FEAT_DIM,
                                   nullptr, nullptr, nullptr, nullptr, 0,
                                   nullptr, nullptr, 0);
    scan_k<<<1, 1024>>>();
    selfloop_k<<<div_up(N_NODES, 256), 256>>>();
    scatter_k<<<edgeGrid, 256>>>(edge_index, edge_w);
    deg_k<<<warpGrid, 256>>>();
    csnorm_k<<<warpGrid, 256>>>();

    gcn_agg_h4<<<aggGrid, 256>>>(xwh_p, b_in, x_p, 1);

    for (int l = 0; l < NLAYERS; l++) {
        // GCN half: gemm (prev GAT norm fused for l>0)
        if (l == 0)
            gemm_h16_db<<<gemmGrid, 256>>>(x_p, nullptr, gcn_W, xwh_p, N_NODES, CCH, CCH,
                                           nullptr, nullptr, nullptr, nullptr, 0,
                                           nullptr, nullptr, 0);
        else
            gemm_h16_db<<<gemmGrid, 256>>>(nullptr, nullptr, gcn_W + l * CCH * CCH, xwh_p,
                                           N_NODES, CCH, CCH,
                                           y_p, x_p,
                                           gn_gamma + (l - 1) * CCH, gn_beta + (l - 1) * CCH, 1,
                                           nullptr, nullptr, 0);
        gcn_agg_h4<<<aggGrid, 256>>>(xwh_p, gcn_b + l * CCH, y_p, 0);
        norm_reduce<<<592, 128>>>(y_p);
        norm_final<<<1, 128>>>(gn_alpha + l * CCH);

        // GAT half: gemm with fused GCN norm + alar epilogue
        gemm_h16_db<<<gemmGrid, 256>>>(nullptr, nullptr, gat_W + l * CCH * CCH, xwh_p,
                                       N_NODES, CCH, CCH,
                                       y_p, x_p,
                                       gn_gamma + l * CCH, gn_beta + l * CCH, 1,
                                       gat_asrc + l * CCH, gat_adst + l * CCH, 1);
        gat_agg_h4<<<aggGrid, 256>>>(xwh_p, gat_b + l * CCH, y_p);
        norm_reduce<<<592, 128>>>(y_p);
        norm_final<<<1, 128>>>(gn_alpha + l * CCH);
    }

    // output conv (final norm fused) + FC head
    gemv_out_f<<<warpGrid, 256>>>(x_p, y_p, gn_gamma + 4 * CCH, gn_beta + 4 * CCH, Wout);
    scalar_agg<<<warpGrid, 256>>>(b_out);
    fc1_partial<<<592, 128>>>(fc_W1);
    fc1_final<<<1, 128>>>(fc_b1);
    fc2_k<<<div_up(POI_LEN_, 128), 128>>>(fc_W2, fc_b2, out);
}

// round 16
// speedup vs baseline: 1.0546x; 1.0388x over previous
#include <cuda_runtime.h>
#include <cuda_fp16.h>
#include <mma.h>
#include <math.h>

using namespace nvcuda;

#define N_NODES 38332
#define N_PAD   38400
#define POI_LEN_ 38333
#define POI_DIM 300
#define CAT_DIM 100
#define FEAT_DIM 403
#define FD_PAD  416
#define CCH 128
#define NLAYERS 5
#define NEDGES 1200000
#define TOTE (NEDGES + N_NODES)
#define NEG 0.01f
#define GAT_NEG 0.2f
#define FULLM 0xffffffffu

// ---------------- scratch (static __device__, no allocation) ----------------
__device__ __half d_feath[N_NODES * FD_PAD];
__device__ float  d_x [N_NODES * CCH];
__device__ __half d_xwh[N_PAD * CCH];
__device__ float  d_y [N_NODES * CCH];
__device__ int    d_csr_src [TOTE];
__device__ float  d_csr_w   [TOTE];
__device__ float  d_csr_norm[TOTE];
__device__ int    d_row_ptr[N_NODES + 1];
__device__ int    d_cnt   [N_NODES];
__device__ int    d_cursor[N_NODES];
__device__ float  d_dinv[N_NODES];
__device__ float  d_al [N_NODES];
__device__ float  d_ar [N_NODES];
__device__ float  d_xw1[N_NODES];
__device__ float  d_xs [N_NODES];
__device__ float  d_stat[2 * CCH];
__device__ float  d_shift[CCH];
__device__ float  d_rstd [CCH];
__device__ float  d_hraw[CCH];
__device__ float  d_h   [CCH];

__device__ __forceinline__ float leaky01(float v) { return v > 0.f ? v : NEG * v; }
__device__ __forceinline__ float leaky20(float v) { return v > 0.f ? v : GAT_NEG * v; }

__device__ __forceinline__ float4 h4_to_f4(uint2 u) {
    float4 r;
    asm("{\n\t"
        ".reg .b16 a, b, c, d;\n\t"
        "mov.b32 {a, b}, %4;\n\t"
        "mov.b32 {c, d}, %5;\n\t"
        "cvt.f32.f16 %0, a;\n\t"
        "cvt.f32.f16 %1, b;\n\t"
        "cvt.f32.f16 %2, c;\n\t"
        "cvt.f32.f16 %3, d;\n\t"
        "}"
        : "=f"(r.x), "=f"(r.y), "=f"(r.z), "=f"(r.w)
        : "r"(u.x), "r"(u.y));
    return r;
}

__device__ __forceinline__ uint2 f4_to_h4(float4 v) {
    __half2 h0 = __floats2half2_rn(v.x, v.y);
    __half2 h1 = __floats2half2_rn(v.z, v.w);
    return make_uint2(*(unsigned*)&h0, *(unsigned*)&h1);
}

// ---------------- CSR build ----------------
__global__ void init_k() {
    int i = blockIdx.x * blockDim.x + threadIdx.x;
    if (i < N_NODES) d_cnt[i] = 1;
    if (i < CCH)     d_hraw[i] = 0.f;
    if (i < 2 * CCH) d_stat[i] = 0.f;
}

__global__ void hist_k(const int* __restrict__ ei) {
    int e = blockIdx.x * blockDim.x + threadIdx.x;
    if (e < NEDGES) atomicAdd(&d_cnt[ei[NEDGES + e]], 1);
}

__global__ void scan_k() {
    const int T = 1024;
    const int ITEMS = (N_NODES + T - 1) / T;
    int tid = threadIdx.x;
    int start = tid * ITEMS;
    int end   = min(start + ITEMS, N_NODES);
    int s = 0;
    for (int i = start; i < end; i++) s += d_cnt[i];
    __shared__ int ps[T];
    ps[tid] = s; __syncthreads();
    for (int off = 1; off < T; off <<= 1) {
        int v = (tid >= off) ? ps[tid - off] : 0;
        __syncthreads();
        ps[tid] += v;
        __syncthreads();
    }
    int incl = ps[tid];
    int run  = incl - s;
    for (int i = start; i < end; i++) { d_row_ptr[i] = run; run += d_cnt[i]; }
    if (tid == T - 1) d_row_ptr[N_NODES] = incl;
}

__global__ void selfloop_k() {
    int i = blockIdx.x * blockDim.x + threadIdx.x;
    if (i < N_NODES) {
        int p = d_row_ptr[i];
        d_csr_src[p] = i;
        d_csr_w[p]   = 1.0f;
        d_cursor[i]  = p + 1;
    }
}

__global__ void scatter_k(const int* __restrict__ ei, const float* __restrict__ ew) {
    int e = blockIdx.x * blockDim.x + threadIdx.x;
    if (e < NEDGES) {
        int dst = ei[NEDGES + e];
        int p = atomicAdd(&d_cursor[dst], 1);
        d_csr_src[p] = ei[e];
        d_csr_w[p]   = ew[e];
    }
}

__global__ void deg_k() {
    int g = blockIdx.x * blockDim.x + threadIdx.x;
    int node = g >> 5, lane = g & 31;
    if (node >= N_NODES) return;
    int s = d_row_ptr[node], e = d_row_ptr[node + 1];
    float acc = 0.f;
    for (int j = s + lane; j < e; j += 32) acc += d_csr_w[j];
    #pragma unroll
    for (int off = 16; off; off >>= 1) acc += __shfl_down_sync(FULLM, acc, off);
    if (lane == 0) d_dinv[node] = rsqrtf(acc);
}

__global__ void csnorm_k() {
    int g = blockIdx.x * blockDim.x + threadIdx.x;
    int node = g >> 5, lane = g & 31;
    if (node >= N_NODES) return;
    int s = d_row_ptr[node], e = d_row_ptr[node + 1];
    float dv = d_dinv[node];
    for (int j = s + lane; j < e; j += 32)
        d_csr_norm[j] = d_dinv[d_csr_src[j]] * d_csr_w[j] * dv;
}

// ---------------- feature assembly (fp16, padded) ----------------
__global__ void feat_k(const int* __restrict__ poi_ids, const int* __restrict__ cat_ids,
                       const float* __restrict__ feat3,
                       const float* __restrict__ poi_emb, const float* __restrict__ cat_emb) {
    int node = blockIdx.x, tid = threadIdx.x;
    int pid = poi_ids[node], cid = cat_ids[node];
    __half* f = d_feath + (size_t)node * FD_PAD;
    for (int k = tid; k < POI_DIM; k += 128) f[k] = __float2half_rn(poi_emb[(size_t)pid * POI_DIM + k]);
    for (int k = tid; k < CAT_DIM; k += 128) f[POI_DIM + k] = __float2half_rn(cat_emb[cid * CAT_DIM + k]);
    if (tid < 3)  f[400 + tid] = __float2half_rn(feat3[node * 3 + tid]);
    if (tid >= 3 && tid < 16) f[400 + tid] = __float2half_rn(0.f);
}

// ---------------- GEMM (fp16 HMMA, double-buffered, fused norm loader) --------------
#define GM 64
#define GN 128
#define GK 16
#define XS_LD 24
#define WS_LD 136
#define EPI_LD 132

#define XS_BYTES (2 * GM * XS_LD * 2)
#define WS_BYTES (2 * GK * WS_LD * 2)
#define SMEM_BYTES (XS_BYTES + WS_BYTES)

__global__ __launch_bounds__(256) void gemm_h16_db(
    const float* __restrict__ X, const __half* __restrict__ Xh,
    const float* __restrict__ W, __half* __restrict__ Yh,
    int n, int K, int Kw,
    const float* __restrict__ yin, float* __restrict__ xio,
    const float* __restrict__ gamma, const float* __restrict__ beta, int fuse_norm,
    const float* __restrict__ asrc, const float* __restrict__ adst, int fuse_alar) {
    __shared__ __align__(16) char smem_raw[SMEM_BYTES];
    typedef __half XsRow[GM][XS_LD];
    typedef __half WsRow[GK][WS_LD];
    XsRow* Xs = reinterpret_cast<XsRow*>(smem_raw);
    WsRow* Ws = reinterpret_cast<WsRow*>(smem_raw + XS_BYTES);
    float (*Epi)[EPI_LD] = reinterpret_cast<float (*)[EPI_LD]>(smem_raw);
    __shared__ float asS[CCH], adS[CCH];
    __shared__ float gS[CCH], bS[CCH], shS[CCH], rsS[CCH];

    int tid = threadIdx.x;
    int warp = tid >> 5;
    int wm = warp & 1;
    int wn = warp >> 1;
    int row0 = blockIdx.x * GM;

    if (fuse_alar && tid < CCH) { asS[tid] = asrc[tid]; adS[tid] = adst[tid]; }
    if (fuse_norm) {
        if (tid < CCH) {
            gS[tid] = gamma[tid]; bS[tid] = beta[tid];
            shS[tid] = d_shift[tid]; rsS[tid] = d_rstd[tid];
        }
        __syncthreads();
    }

    wmma::fragment<wmma::accumulator, 16, 16, 16, float> c[2][2];
    #pragma unroll
    for (int i = 0; i < 2; i++)
        #pragma unroll
        for (int j = 0; j < 2; j++) wmma::fill_fragment(c[i][j], 0.f);

    int nIter = (K + GK - 1) / GK;

    int rX = tid >> 2;
    int kX = (tid & 3) * 4;
    int gr = row0 + rX;
    uint2 xr; uint2 wr[2];

    auto loadX = [&](int gk0) -> uint2 {
        if (fuse_norm) {
            if (gr < n) {
                size_t off = (size_t)gr * CCH + gk0;
                float4 yv = *(const float4*)(yin + off);
                float4 xv = *(const float4*)(xio + off);
                float4 v;
                v.x = xv.x + leaky01(gS[gk0]     * (yv.x - shS[gk0])     * rsS[gk0]     + bS[gk0]);
                v.y = xv.y + leaky01(gS[gk0 + 1] * (yv.y - shS[gk0 + 1]) * rsS[gk0 + 1] + bS[gk0 + 1]);
                v.z = xv.z + leaky01(gS[gk0 + 2] * (yv.z - shS[gk0 + 2]) * rsS[gk0 + 2] + bS[gk0 + 2]);
                v.w = xv.w + leaky01(gS[gk0 + 3] * (yv.w - shS[gk0 + 3]) * rsS[gk0 + 3] + bS[gk0 + 3]);
                *(float4*)(xio + off) = v;
                return f4_to_h4(v);
            }
            return make_uint2(0u, 0u);
        }
        if (Xh) {
            if (gr < n) return *(const uint2*)(Xh + (size_t)gr * K + gk0);
            return make_uint2(0u, 0u);
        }
        float xv[4];
        #pragma unroll
        for (int t = 0; t < 4; t++) {
            int gk = gk0 + t;
            xv[t] = (gr < n && gk < K) ? X[(size_t)gr * K + gk] : 0.f;
        }
        return f4_to_h4(make_float4(xv[0], xv[1], xv[2], xv[3]));
    };

    xr = loadX(kX);
    #pragma unroll
    for (int i = 0; i < 2; i++) {
        int e = (tid + i * 256) * 4;
        int rW = e >> 7, cW = e & 127;
        float4 v = (rW < Kw) ? *(const float4*)(W + (size_t)rW * GN + cW)
                             : make_float4(0.f, 0.f, 0.f, 0.f);
        wr[i] = f4_to_h4(v);
    }

    for (int it = 0; it < nIter; it++) {
        int cur = it & 1;
        *(uint2*)&Xs[cur][rX][kX] = xr;
        #pragma unroll
        for (int i = 0; i < 2; i++) {
            int e = (tid + i * 256) * 4;
            int rW = e >> 7, cW = e & 127;
            *(uint2*)&Ws[cur][rW][cW] = wr[i];
        }
        __syncthreads();
        if (it + 1 < nIter) {
            int k0 = (it + 1) * GK;
            xr = loadX(k0 + kX);
            #pragma unroll
            for (int i = 0; i < 2; i++) {
                int e = (tid + i * 256) * 4;
                int rW = e >> 7, cW = e & 127;
                int gk = k0 + rW;
                float4 v = (gk < Kw) ? *(const float4*)(W + (size_t)gk * GN + cW)
                                     : make_float4(0.f, 0.f, 0.f, 0.f);
                wr[i] = f4_to_h4(v);
            }
        }
        wmma::fragment<wmma::matrix_a, 16, 16, 16, __half, wmma::row_major> a[2];
        wmma::fragment<wmma::matrix_b, 16, 16, 16, __half, wmma::row_major> bf[2];
        #pragma unroll
        for (int i = 0; i < 2; i++)
            wmma::load_matrix_sync(a[i], &Xs[cur][wm * 32 + i * 16][0], XS_LD);
        #pragma unroll
        for (int j = 0; j < 2; j++)
            wmma::load_matrix_sync(bf[j], &Ws[cur][0][wn * 32 + j * 16], WS_LD);
        #pragma unroll
        for (int i = 0; i < 2; i++)
            #pragma unroll
            for (int j = 0; j < 2; j++)
                wmma::mma_sync(c[i][j], a[i], bf[j], c[i][j]);
    }
    __syncthreads();

    int rhalf = tid >> 4;
    int lane16 = tid & 15;
    #pragma unroll
    for (int p = 0; p < 4; p++) {
        if (wm == (p >> 1)) {
            int i = p & 1;
            wmma::store_matrix_sync(&Epi[0][wn * 32],      c[i][0], EPI_LD, wmma::mem_row_major);
            wmma::store_matrix_sync(&Epi[0][wn * 32 + 16], c[i][1], EPI_LD, wmma::mem_row_major);
        }
        __syncthreads();
        int grow = row0 + p * 16 + rhalf;
        int c0 = lane16 * 8;
        float4 v0 = *(const float4*)&Epi[rhalf][c0];
        float4 v1 = *(const float4*)&Epi[rhalf][c0 + 4];
        uint2 o0 = f4_to_h4(v0);
        uint2 o1 = f4_to_h4(v1);
        *(uint4*)(Yh + (size_t)grow * CCH + c0) = make_uint4(o0.x, o0.y, o1.x, o1.y);
        if (fuse_alar) {
            float al = v0.x * asS[c0]     + v0.y * asS[c0 + 1] + v0.z * asS[c0 + 2] + v0.w * asS[c0 + 3]
                     + v1.x * asS[c0 + 4] + v1.y * asS[c0 + 5] + v1.z * asS[c0 + 6] + v1.w * asS[c0 + 7];
            float ar = v0.x * adS[c0]     + v0.y * adS[c0 + 1] + v0.z * adS[c0 + 2] + v0.w * adS[c0 + 3]
                     + v1.x * adS[c0 + 4] + v1.y * adS[c0 + 5] + v1.z * adS[c0 + 6] + v1.w * adS[c0 + 7];
            #pragma unroll
            for (int off = 8; off; off >>= 1) {
                al += __shfl_down_sync(FULLM, al, off, 16);
                ar += __shfl_down_sync(FULLM, ar, off, 16);
            }
            if (lane16 == 0 && grow < n) { d_al[grow] = al; d_ar[grow] = ar; }
        }
        __syncthreads();
    }
}

// ---------------- GCN aggregation: warp/node, fp16 gather, 4-way MLP (R12) ----------
__global__ __launch_bounds__(256) void gcn_agg_h2(const __half* __restrict__ xwh,
                                                  const float* __restrict__ b,
                                                  float* __restrict__ y, int do_leaky) {
    int node = (blockIdx.x * blockDim.x + threadIdx.x) >> 5;
    int lane = threadIdx.x & 31;
    if (node >= N_NODES) return;
    int s = d_row_ptr[node], e = d_row_ptr[node + 1];
    float4 acc = make_float4(0.f, 0.f, 0.f, 0.f);
    for (int base = s; base < e; base += 32) {
        int j = base + lane;
        int srcL = 0; float nrmL = 0.f;
        if (j < e) { srcL = d_csr_src[j]; nrmL = d_csr_norm[j]; }
        int cnt = min(32, e - base);
        int q = 0;
        for (; q + 4 <= cnt; q += 4) {
            int s0 = __shfl_sync(FULLM, srcL, q);
            int s1 = __shfl_sync(FULLM, srcL, q + 1);
            int s2 = __shfl_sync(FULLM, srcL, q + 2);
            int s3 = __shfl_sync(FULLM, srcL, q + 3);
            float n0 = __shfl_sync(FULLM, nrmL, q);
            float n1 = __shfl_sync(FULLM, nrmL, q + 1);
            float n2 = __shfl_sync(FULLM, nrmL, q + 2);
            float n3 = __shfl_sync(FULLM, nrmL, q + 3);
            uint2 u0 = ((const uint2*)(xwh + (size_t)s0 * CCH))[lane];
            uint2 u1 = ((const uint2*)(xwh + (size_t)s1 * CCH))[lane];
            uint2 u2 = ((const uint2*)(xwh + (size_t)s2 * CCH))[lane];
            uint2 u3 = ((const uint2*)(xwh + (size_t)s3 * CCH))[lane];
            float4 v0 = h4_to_f4(u0);
            acc.x += n0 * v0.x; acc.y += n0 * v0.y; acc.z += n0 * v0.z; acc.w += n0 * v0.w;
            float4 v1 = h4_to_f4(u1);
            acc.x += n1 * v1.x; acc.y += n1 * v1.y; acc.z += n1 * v1.z; acc.w += n1 * v1.w;
            float4 v2 = h4_to_f4(u2);
            acc.x += n2 * v2.x; acc.y += n2 * v2.y; acc.z += n2 * v2.z; acc.w += n2 * v2.w;
            float4 v3 = h4_to_f4(u3);
            acc.x += n3 * v3.x; acc.y += n3 * v3.y; acc.z += n3 * v3.z; acc.w += n3 * v3.w;
        }
        for (; q < cnt; q++) {
            int   sq = __shfl_sync(FULLM, srcL, q);
            float nq = __shfl_sync(FULLM, nrmL, q);
            uint2 u = ((const uint2*)(xwh + (size_t)sq * CCH))[lane];
            float4 v = h4_to_f4(u);
            acc.x += nq * v.x; acc.y += nq * v.y;
            acc.z += nq * v.z; acc.w += nq * v.w;
        }
    }
    float4 bb = ((const float4*)b)[lane];
    acc.x += bb.x; acc.y += bb.y; acc.z += bb.z; acc.w += bb.w;
    if (do_leaky) {
        acc.x = leaky01(acc.x); acc.y = leaky01(acc.y);
        acc.z = leaky01(acc.z); acc.w = leaky01(acc.w);
    }
    ((float4*)(y + (size_t)node * CCH))[lane] = acc;
}

// ---------------- GAT aggregation: warp/node, fp16 gather, 4-way MLP (R12) ----------
__global__ __launch_bounds__(256) void gat_agg_h2(const __half* __restrict__ xwh,
                                                  const float* __restrict__ b,
                                                  float* __restrict__ y) {
    int node = (blockIdx.x * blockDim.x + threadIdx.x) >> 5;
    int lane = threadIdx.x & 31;
    if (node >= N_NODES) return;
    int s = d_row_ptr[node], e = d_row_ptr[node + 1];
    float arn = d_ar[node];

    float m = -1e30f;
    for (int j = s + lane; j < e; j += 32)
        m = fmaxf(m, leaky20(d_al[d_csr_src[j]] + arn));
    #pragma unroll
    for (int off = 16; off; off >>= 1) m = fmaxf(m, __shfl_xor_sync(FULLM, m, off));

    float denom = 0.f;
    float4 acc = make_float4(0.f, 0.f, 0.f, 0.f);
    for (int base = s; base < e; base += 32) {
        int j = base + lane;
        int srcL = 0; float exL = 0.f;
        if (j < e) {
            srcL = d_csr_src[j];
            exL = __expf(leaky20(d_al[srcL] + arn) - m);
            denom += exL;
        }
        int cnt = min(32, e - base);
        int q = 0;
        for (; q + 4 <= cnt; q += 4) {
            int s0 = __shfl_sync(FULLM, srcL, q);
            int s1 = __shfl_sync(FULLM, srcL, q + 1);
            int s2 = __shfl_sync(FULLM, srcL, q + 2);
            int s3 = __shfl_sync(FULLM, srcL, q + 3);
            float a0 = __shfl_sync(FULLM, exL, q);
            float a1 = __shfl_sync(FULLM, exL, q + 1);
            float a2 = __shfl_sync(FULLM, exL, q + 2);
            float a3 = __shfl_sync(FULLM, exL, q + 3);
            uint2 u0 = ((const uint2*)(xwh + (size_t)s0 * CCH))[lane];
            uint2 u1 = ((const uint2*)(xwh + (size_t)s1 * CCH))[lane];
            uint2 u2 = ((const uint2*)(xwh + (size_t)s2 * CCH))[lane];
            uint2 u3 = ((const uint2*)(xwh + (size_t)s3 * CCH))[lane];
            float4 v0 = h4_to_f4(u0);
            acc.x += a0 * v0.x; acc.y += a0 * v0.y; acc.z += a0 * v0.z; acc.w += a0 * v0.w;
            float4 v1 = h4_to_f4(u1);
            acc.x += a1 * v1.x; acc.y += a1 * v1.y; acc.z += a1 * v1.z; acc.w += a1 * v1.w;
            float4 v2 = h4_to_f4(u2);
            acc.x += a2 * v2.x; acc.y += a2 * v2.y; acc.z += a2 * v2.z; acc.w += a2 * v2.w;
            float4 v3 = h4_to_f4(u3);
            acc.x += a3 * v3.x; acc.y += a3 * v3.y; acc.z += a3 * v3.z; acc.w += a3 * v3.w;
        }
        for (; q < cnt; q++) {
            int   sq = __shfl_sync(FULLM, srcL, q);
            float aq = __shfl_sync(FULLM, exL, q);
            uint2 u = ((const uint2*)(xwh + (size_t)sq * CCH))[lane];
            float4 v = h4_to_f4(u);
            acc.x += aq * v.x; acc.y += aq * v.y;
            acc.z += aq * v.z; acc.w += aq * v.w;
        }
    }
    #pragma unroll
    for (int off = 16; off; off >>= 1) denom += __shfl_xor_sync(FULLM, denom, off);
    float inv = 1.f / denom;

    float4 bb = ((const float4*)b)[lane];
    ((float4*)(y + (size_t)node * CCH))[lane] =
        make_float4(acc.x * inv + bb.x, acc.y * inv + bb.y,
                    acc.z * inv + bb.z, acc.w * inv + bb.w);
}

// ---------------- GraphNorm stats ----------------
__global__ void norm_reduce(const float* __restrict__ y) {
    int c = threadIdx.x;
    float ls = 0.f, lq = 0.f;
    for (int n = blockIdx.x; n < N_NODES; n += gridDim.x) {
        float v = y[(long)n * CCH + c];
        ls += v; lq += v * v;
    }
    atomicAdd(&d_stat[c], ls);
    atomicAdd(&d_stat[CCH + c], lq);
}

__global__ void norm_final(const float* __restrict__ alpha) {
    int c = threadIdx.x;
    float m = d_stat[c] * (1.0f / N_NODES);
    float q = d_stat[CCH + c] * (1.0f / N_NODES);
    float a = alpha[c];
    float var = q - (2.f * a - a * a) * m * m;
    d_shift[c] = a * m;
    d_rstd[c]  = rsqrtf(var + 1e-5f);
    d_stat[c] = 0.f;
    d_stat[CCH + c] = 0.f;
}

// ---------------- output head ----------------
__global__ void gemv_out_f(const float* __restrict__ x, const float* __restrict__ yin,
                           const float* __restrict__ gamma, const float* __restrict__ beta,
                           const float* __restrict__ Wout) {
    int g = blockIdx.x * blockDim.x + threadIdx.x;
    int node = g >> 5, lane = g & 31;
    if (node >= N_NODES) return;
    float4 xv = ((const float4*)(x + (size_t)node * CCH))[lane];
    float4 yv = ((const float4*)(yin + (size_t)node * CCH))[lane];
    float4 gm = ((const float4*)gamma)[lane];
    float4 bt = ((const float4*)beta)[lane];
    float4 sh = ((const float4*)d_shift)[lane];
    float4 rs = ((const float4*)d_rstd)[lane];
    float4 w  = ((const float4*)Wout)[lane];
    float vx = xv.x + leaky01(gm.x * (yv.x - sh.x) * rs.x + bt.x);
    float vy = xv.y + leaky01(gm.y * (yv.y - sh.y) * rs.y + bt.y);
    float vz = xv.z + leaky01(gm.z * (yv.z - sh.z) * rs.z + bt.z);
    float vw = xv.w + leaky01(gm.w * (yv.w - sh.w) * rs.w + bt.w);
    float d = vx * w.x + vy * w.y + vz * w.z + vw * w.w;
    #pragma unroll
    for (int off = 16; off; off >>= 1) d += __shfl_down_sync(FULLM, d, off);
    if (lane == 0) d_xw1[node] = d;
}

__global__ void scalar_agg(const float* __restrict__ b_out) {
    int g = blockIdx.x * blockDim.x + threadIdx.x;
    int node = g >> 5, lane = g & 31;
    if (node >= N_NODES) return;
    int s = d_row_ptr[node], e = d_row_ptr[node + 1];
    float acc = 0.f;
    for (int j = s + lane; j < e; j += 32)
        acc += d_csr_norm[j] * d_xw1[d_csr_src[j]];
    #pragma unroll
    for (int off = 16; off; off >>= 1) acc += __shfl_down_sync(FULLM, acc, off);
    if (lane == 0) d_xs[node] = leaky01(acc + b_out[0]);
}

__global__ void fc1_partial(const float* __restrict__ W1) {
    int c = threadIdx.x;
    float acc = 0.f;
    for (int n = blockIdx.x; n < N_NODES; n += gridDim.x)
        acc += d_xs[n] * W1[(long)n * CCH + c];
    atomicAdd(&d_hraw[c], acc);
}

__global__ void fc1_final(const float* __restrict__ b1) {
    int c = threadIdx.x;
    float v = d_hraw[c] + b1[c];
    d_h[c] = v > 0.f ? v : 0.f;
}

__global__ void fc2_k(const float* __restrict__ W2, const float* __restrict__ b2,
                      float* __restrict__ out) {
    __shared__ float hs[CCH];
    int tid = threadIdx.x;
    hs[tid] = d_h[tid];
    __syncthreads();
    int p = blockIdx.x * 128 + tid;
    if (p >= POI_LEN_) return;
    float acc = b2[p];
    #pragma unroll 8
    for (int j = 0; j < CCH; j++)
        acc += hs[j] * W2[(long)j * POI_LEN_ + p];
    out[p] = acc > 0.f ? acc : 0.f;
}

// ---------------- launch ----------------
static inline int div_up(int a, int b) { return (a + b - 1) / b; }

extern "C" void kernel_launch(void* const* d_in, const int* in_sizes, int n_in,
                              void* d_out, int out_size) {
    const int*   poi_ids   = (const int*)  d_in[0];
    const int*   cat_ids   = (const int*)  d_in[1];
    const float* feat3     = (const float*)d_in[2];
    const int*   edge_index= (const int*)  d_in[3];
    const float* edge_w    = (const float*)d_in[4];
    const float* poi_emb   = (const float*)d_in[5];
    const float* cat_emb   = (const float*)d_in[6];
    const float* Win       = (const float*)d_in[7];
    const float* b_in      = (const float*)d_in[8];
    const float* gcn_W     = (const float*)d_in[9];
    const float* gcn_b     = (const float*)d_in[10];
    const float* gn_gamma  = (const float*)d_in[11];
    const float* gn_beta   = (const float*)d_in[12];
    const float* gn_alpha  = (const float*)d_in[13];
    const float* gat_W     = (const float*)d_in[14];
    const float* gat_asrc  = (const float*)d_in[15];
    const float* gat_adst  = (const float*)d_in[16];
    const float* gat_b     = (const float*)d_in[17];
    const float* Wout      = (const float*)d_in[18];
    const float* b_out     = (const float*)d_in[19];
    const float* fc_W1     = (const float*)d_in[20];
    const float* fc_b1     = (const float*)d_in[21];
    const float* fc_W2     = (const float*)d_in[22];
    const float* fc_b2     = (const float*)d_in[23];
    float* out = (float*)d_out;

    float *x_p, *y_p; __half *xwh_p, *feath_p;
    cudaGetSymbolAddress((void**)&x_p,  d_x);
    cudaGetSymbolAddress((void**)&y_p,  d_y);
    cudaGetSymbolAddress((void**)&xwh_p, d_xwh);
    cudaGetSymbolAddress((void**)&feath_p, d_feath);

    const int warpGrid = div_up(N_NODES * 32, 256);
    const int edgeGrid = div_up(NEDGES, 256);
    const int gemmGrid = N_PAD / GM;               // 600
    const int aggGrid  = div_up(N_NODES, 8);       // warp per node

    feat_k<<<N_NODES, 128>>>(poi_ids, cat_ids, feat3, poi_emb, cat_emb);
    init_k<<<div_up(N_NODES, 256), 256>>>();
    hist_k<<<edgeGrid, 256>>>(edge_index);
    gemm_h16_db<<<gemmGrid, 256>>>(nullptr, feath_p, Win, xwh_p, N_NODES, FD_PAD, FEAT_DIM,
                                   nullptr, nullptr, nullptr, nullptr, 0,
                                   nullptr, nullptr, 0);
    scan_k<<<1, 1024>>>();
    selfloop_k<<<div_up(N_NODES, 256), 256>>>();
    scatter_k<<<edgeGrid, 256>>>(edge_index, edge_w);
    deg_k<<<warpGrid, 256>>>();
    csnorm_k<<<warpGrid, 256>>>();

    gcn_agg_h2<<<aggGrid, 256>>>(xwh_p, b_in, x_p, 1);

    for (int l = 0; l < NLAYERS; l++) {
        // GCN half: gemm (prev GAT norm fused for l>0)
        if (l == 0)
            gemm_h16_db<<<gemmGrid, 256>>>(x_p, nullptr, gcn_W, xwh_p, N_NODES, CCH, CCH,
                                           nullptr, nullptr, nullptr, nullptr, 0,
                                           nullptr, nullptr, 0);
        else
            gemm_h16_db<<<gemmGrid, 256>>>(nullptr, nullptr, gcn_W + l * CCH * CCH, xwh_p,
                                           N_NODES, CCH, CCH,
                                           y_p, x_p,
                                           gn_gamma + (l - 1) * CCH, gn_beta + (l - 1) * CCH, 1,
                                           nullptr, nullptr, 0);
        gcn_agg_h2<<<aggGrid, 256>>>(xwh_p, gcn_b + l * CCH, y_p, 0);
        norm_reduce<<<592, 128>>>(y_p);
        norm_final<<<1, 128>>>(gn_alpha + l * CCH);

        // GAT half: gemm with fused GCN norm + alar epilogue
        gemm_h16_db<<<gemmGrid, 256>>>(nullptr, nullptr, gat_W + l * CCH * CCH, xwh_p,
                                       N_NODES, CCH, CCH,
                                       y_p, x_p,
                                       gn_gamma + l * CCH, gn_beta + l * CCH, 1,
                                       gat_asrc + l * CCH, gat_adst + l * CCH, 1);
        gat_agg_h2<<<aggGrid, 256>>>(xwh_p, gat_b + l * CCH, y_p);
        norm_reduce<<<592, 128>>>(y_p);
        norm_final<<<1, 128>>>(gn_alpha + l * CCH);
    }

    // output conv (final norm fused) + FC head
    gemv_out_f<<<warpGrid, 256>>>(x_p, y_p, gn_gamma + 4 * CCH, gn_beta + 4 * CCH, Wout);
    scalar_agg<<<warpGrid, 256>>>(b_out);
    fc1_partial<<<592, 128>>>(fc_W1);
    fc1_final<<<1, 128>>>(fc_b1);
    fc2_k<<<div_up(POI_LEN_, 128), 128>>>(fc_W2, fc_b2, out);
}

// round 17
// speedup vs baseline: 1.0806x; 1.0246x over previous
#include <cuda_runtime.h>
#include <cuda_fp16.h>
#include <mma.h>
#include <math.h>

using namespace nvcuda;

#define N_NODES 38332
#define N_PAD   38400
#define POI_LEN_ 38333
#define POI_DIM 300
#define CAT_DIM 100
#define FEAT_DIM 403
#define FD_PAD  416
#define CCH 128
#define NLAYERS 5
#define NEDGES 1200000
#define TOTE (NEDGES + N_NODES)
#define NEG 0.01f
#define GAT_NEG 0.2f
#define FULLM 0xffffffffu

// ---------------- scratch (static __device__, no allocation) ----------------
__device__ __half d_feath[N_NODES * FD_PAD];
__device__ __half d_x [N_NODES * CCH];      // fp16 residual state
__device__ __half d_xwh[N_PAD * CCH];
__device__ __half d_y [N_NODES * CCH];      // fp16 pre-norm activations
__device__ int    d_csr_src [TOTE];
__device__ float  d_csr_w   [TOTE];
__device__ float  d_csr_norm[TOTE];
__device__ int    d_row_ptr[N_NODES + 1];
__device__ int    d_cnt   [N_NODES];
__device__ int    d_cursor[N_NODES];
__device__ float  d_dinv[N_NODES];
__device__ float  d_al [N_NODES];
__device__ float  d_ar [N_NODES];
__device__ float  d_xw1[N_NODES];
__device__ float  d_xs [N_NODES];
__device__ float  d_stat[2 * CCH];
__device__ float  d_shift[CCH];
__device__ float  d_rstd [CCH];
__device__ float  d_hraw[CCH];
__device__ float  d_h   [CCH];

__device__ __forceinline__ float leaky01(float v) { return v > 0.f ? v : NEG * v; }
__device__ __forceinline__ float leaky20(float v) { return v > 0.f ? v : GAT_NEG * v; }

__device__ __forceinline__ float4 h4_to_f4(uint2 u) {
    float4 r;
    asm("{\n\t"
        ".reg .b16 a, b, c, d;\n\t"
        "mov.b32 {a, b}, %4;\n\t"
        "mov.b32 {c, d}, %5;\n\t"
        "cvt.f32.f16 %0, a;\n\t"
        "cvt.f32.f16 %1, b;\n\t"
        "cvt.f32.f16 %2, c;\n\t"
        "cvt.f32.f16 %3, d;\n\t"
        "}"
        : "=f"(r.x), "=f"(r.y), "=f"(r.z), "=f"(r.w)
        : "r"(u.x), "r"(u.y));
    return r;
}

__device__ __forceinline__ uint2 f4_to_h4(float4 v) {
    __half2 h0 = __floats2half2_rn(v.x, v.y);
    __half2 h1 = __floats2half2_rn(v.z, v.w);
    return make_uint2(*(unsigned*)&h0, *(unsigned*)&h1);
}

// ---------------- CSR build ----------------
__global__ void init_k() {
    int i = blockIdx.x * blockDim.x + threadIdx.x;
    if (i < N_NODES) d_cnt[i] = 1;
    if (i < CCH)     d_hraw[i] = 0.f;
    if (i < 2 * CCH) d_stat[i] = 0.f;
}

__global__ void hist_k(const int* __restrict__ ei) {
    int e = blockIdx.x * blockDim.x + threadIdx.x;
    if (e < NEDGES) atomicAdd(&d_cnt[ei[NEDGES + e]], 1);
}

__global__ void scan_k() {
    const int T = 1024;
    const int ITEMS = (N_NODES + T - 1) / T;
    int tid = threadIdx.x;
    int start = tid * ITEMS;
    int end   = min(start + ITEMS, N_NODES);
    int s = 0;
    for (int i = start; i < end; i++) s += d_cnt[i];
    __shared__ int ps[T];
    ps[tid] = s; __syncthreads();
    for (int off = 1; off < T; off <<= 1) {
        int v = (tid >= off) ? ps[tid - off] : 0;
        __syncthreads();
        ps[tid] += v;
        __syncthreads();
    }
    int incl = ps[tid];
    int run  = incl - s;
    for (int i = start; i < end; i++) { d_row_ptr[i] = run; run += d_cnt[i]; }
    if (tid == T - 1) d_row_ptr[N_NODES] = incl;
}

__global__ void selfloop_k() {
    int i = blockIdx.x * blockDim.x + threadIdx.x;
    if (i < N_NODES) {
        int p = d_row_ptr[i];
        d_csr_src[p] = i;
        d_csr_w[p]   = 1.0f;
        d_cursor[i]  = p + 1;
    }
}

__global__ void scatter_k(const int* __restrict__ ei, const float* __restrict__ ew) {
    int e = blockIdx.x * blockDim.x + threadIdx.x;
    if (e < NEDGES) {
        int dst = ei[NEDGES + e];
        int p = atomicAdd(&d_cursor[dst], 1);
        d_csr_src[p] = ei[e];
        d_csr_w[p]   = ew[e];
    }
}

__global__ void deg_k() {
    int g = blockIdx.x * blockDim.x + threadIdx.x;
    int node = g >> 5, lane = g & 31;
    if (node >= N_NODES) return;
    int s = d_row_ptr[node], e = d_row_ptr[node + 1];
    float acc = 0.f;
    for (int j = s + lane; j < e; j += 32) acc += d_csr_w[j];
    #pragma unroll
    for (int off = 16; off; off >>= 1) acc += __shfl_down_sync(FULLM, acc, off);
    if (lane == 0) d_dinv[node] = rsqrtf(acc);
}

__global__ void csnorm_k() {
    int g = blockIdx.x * blockDim.x + threadIdx.x;
    int node = g >> 5, lane = g & 31;
    if (node >= N_NODES) return;
    int s = d_row_ptr[node], e = d_row_ptr[node + 1];
    float dv = d_dinv[node];
    for (int j = s + lane; j < e; j += 32)
        d_csr_norm[j] = d_dinv[d_csr_src[j]] * d_csr_w[j] * dv;
}

// ---------------- feature assembly (fp16, padded) ----------------
__global__ void feat_k(const int* __restrict__ poi_ids, const int* __restrict__ cat_ids,
                       const float* __restrict__ feat3,
                       const float* __restrict__ poi_emb, const float* __restrict__ cat_emb) {
    int node = blockIdx.x, tid = threadIdx.x;
    int pid = poi_ids[node], cid = cat_ids[node];
    __half* f = d_feath + (size_t)node * FD_PAD;
    for (int k = tid; k < POI_DIM; k += 128) f[k] = __float2half_rn(poi_emb[(size_t)pid * POI_DIM + k]);
    for (int k = tid; k < CAT_DIM; k += 128) f[POI_DIM + k] = __float2half_rn(cat_emb[cid * CAT_DIM + k]);
    if (tid < 3)  f[400 + tid] = __float2half_rn(feat3[node * 3 + tid]);
    if (tid >= 3 && tid < 16) f[400 + tid] = __float2half_rn(0.f);
}

// ---------------- GEMM (fp16 HMMA, double-buffered, fused norm loader) --------------
#define GM 64
#define GN 128
#define GK 16
#define XS_LD 24
#define WS_LD 136
#define EPI_LD 132

#define XS_BYTES (2 * GM * XS_LD * 2)
#define WS_BYTES (2 * GK * WS_LD * 2)
#define SMEM_BYTES (XS_BYTES + WS_BYTES)

__global__ __launch_bounds__(256) void gemm_h16_db(
    const __half* __restrict__ Xh,
    const float* __restrict__ W, __half* __restrict__ Yh,
    int n, int K, int Kw,
    const __half* __restrict__ yin, __half* __restrict__ xio,
    const float* __restrict__ gamma, const float* __restrict__ beta, int fuse_norm,
    const float* __restrict__ asrc, const float* __restrict__ adst, int fuse_alar) {
    __shared__ __align__(16) char smem_raw[SMEM_BYTES];
    typedef __half XsRow[GM][XS_LD];
    typedef __half WsRow[GK][WS_LD];
    XsRow* Xs = reinterpret_cast<XsRow*>(smem_raw);
    WsRow* Ws = reinterpret_cast<WsRow*>(smem_raw + XS_BYTES);
    float (*Epi)[EPI_LD] = reinterpret_cast<float (*)[EPI_LD]>(smem_raw);
    __shared__ float asS[CCH], adS[CCH];
    __shared__ float gS[CCH], bS[CCH], shS[CCH], rsS[CCH];

    int tid = threadIdx.x;
    int warp = tid >> 5;
    int wm = warp & 1;
    int wn = warp >> 1;
    int row0 = blockIdx.x * GM;

    if (fuse_alar && tid < CCH) { asS[tid] = asrc[tid]; adS[tid] = adst[tid]; }
    if (fuse_norm) {
        if (tid < CCH) {
            gS[tid] = gamma[tid]; bS[tid] = beta[tid];
            shS[tid] = d_shift[tid]; rsS[tid] = d_rstd[tid];
        }
        __syncthreads();
    }

    wmma::fragment<wmma::accumulator, 16, 16, 16, float> c[2][2];
    #pragma unroll
    for (int i = 0; i < 2; i++)
        #pragma unroll
        for (int j = 0; j < 2; j++) wmma::fill_fragment(c[i][j], 0.f);

    int nIter = (K + GK - 1) / GK;

    int rX = tid >> 2;
    int kX = (tid & 3) * 4;
    int gr = row0 + rX;
    uint2 xr; uint2 wr[2];

    auto loadX = [&](int gk0) -> uint2 {
        if (fuse_norm) {
            if (gr < n) {
                size_t off = (size_t)gr * CCH + gk0;
                float4 yv = h4_to_f4(*(const uint2*)(yin + off));
                float4 xv = h4_to_f4(*(const uint2*)(xio + off));
                float4 v;
                v.x = xv.x + leaky01(gS[gk0]     * (yv.x - shS[gk0])     * rsS[gk0]     + bS[gk0]);
                v.y = xv.y + leaky01(gS[gk0 + 1] * (yv.y - shS[gk0 + 1]) * rsS[gk0 + 1] + bS[gk0 + 1]);
                v.z = xv.z + leaky01(gS[gk0 + 2] * (yv.z - shS[gk0 + 2]) * rsS[gk0 + 2] + bS[gk0 + 2]);
                v.w = xv.w + leaky01(gS[gk0 + 3] * (yv.w - shS[gk0 + 3]) * rsS[gk0 + 3] + bS[gk0 + 3]);
                uint2 o = f4_to_h4(v);
                *(uint2*)(xio + off) = o;
                return o;
            }
            return make_uint2(0u, 0u);
        }
        if (gr < n) return *(const uint2*)(Xh + (size_t)gr * K + gk0);
        return make_uint2(0u, 0u);
    };

    xr = loadX(kX);
    #pragma unroll
    for (int i = 0; i < 2; i++) {
        int e = (tid + i * 256) * 4;
        int rW = e >> 7, cW = e & 127;
        float4 v = (rW < Kw) ? *(const float4*)(W + (size_t)rW * GN + cW)
                             : make_float4(0.f, 0.f, 0.f, 0.f);
        wr[i] = f4_to_h4(v);
    }

    for (int it = 0; it < nIter; it++) {
        int cur = it & 1;
        *(uint2*)&Xs[cur][rX][kX] = xr;
        #pragma unroll
        for (int i = 0; i < 2; i++) {
            int e = (tid + i * 256) * 4;
            int rW = e >> 7, cW = e & 127;
            *(uint2*)&Ws[cur][rW][cW] = wr[i];
        }
        __syncthreads();
        if (it + 1 < nIter) {
            int k0 = (it + 1) * GK;
            xr = loadX(k0 + kX);
            #pragma unroll
            for (int i = 0; i < 2; i++) {
                int e = (tid + i * 256) * 4;
                int rW = e >> 7, cW = e & 127;
                int gk = k0 + rW;
                float4 v = (gk < Kw) ? *(const float4*)(W + (size_t)gk * GN + cW)
                                     : make_float4(0.f, 0.f, 0.f, 0.f);
                wr[i] = f4_to_h4(v);
            }
        }
        wmma::fragment<wmma::matrix_a, 16, 16, 16, __half, wmma::row_major> a[2];
        wmma::fragment<wmma::matrix_b, 16, 16, 16, __half, wmma::row_major> bf[2];
        #pragma unroll
        for (int i = 0; i < 2; i++)
            wmma::load_matrix_sync(a[i], &Xs[cur][wm * 32 + i * 16][0], XS_LD);
        #pragma unroll
        for (int j = 0; j < 2; j++)
            wmma::load_matrix_sync(bf[j], &Ws[cur][0][wn * 32 + j * 16], WS_LD);
        #pragma unroll
        for (int i = 0; i < 2; i++)
            #pragma unroll
            for (int j = 0; j < 2; j++)
                wmma::mma_sync(c[i][j], a[i], bf[j], c[i][j]);
    }
    __syncthreads();

    int rhalf = tid >> 4;
    int lane16 = tid & 15;
    #pragma unroll
    for (int p = 0; p < 4; p++) {
        if (wm == (p >> 1)) {
            int i = p & 1;
            wmma::store_matrix_sync(&Epi[0][wn * 32],      c[i][0], EPI_LD, wmma::mem_row_major);
            wmma::store_matrix_sync(&Epi[0][wn * 32 + 16], c[i][1], EPI_LD, wmma::mem_row_major);
        }
        __syncthreads();
        int grow = row0 + p * 16 + rhalf;
        int c0 = lane16 * 8;
        float4 v0 = *(const float4*)&Epi[rhalf][c0];
        float4 v1 = *(const float4*)&Epi[rhalf][c0 + 4];
        uint2 o0 = f4_to_h4(v0);
        uint2 o1 = f4_to_h4(v1);
        *(uint4*)(Yh + (size_t)grow * CCH + c0) = make_uint4(o0.x, o0.y, o1.x, o1.y);
        if (fuse_alar) {
            float al = v0.x * asS[c0]     + v0.y * asS[c0 + 1] + v0.z * asS[c0 + 2] + v0.w * asS[c0 + 3]
                     + v1.x * asS[c0 + 4] + v1.y * asS[c0 + 5] + v1.z * asS[c0 + 6] + v1.w * asS[c0 + 7];
            float ar = v0.x * adS[c0]     + v0.y * adS[c0 + 1] + v0.z * adS[c0 + 2] + v0.w * adS[c0 + 3]
                     + v1.x * adS[c0 + 4] + v1.y * adS[c0 + 5] + v1.z * adS[c0 + 6] + v1.w * adS[c0 + 7];
            #pragma unroll
            for (int off = 8; off; off >>= 1) {
                al += __shfl_down_sync(FULLM, al, off, 16);
                ar += __shfl_down_sync(FULLM, ar, off, 16);
            }
            if (lane16 == 0 && grow < n) { d_al[grow] = al; d_ar[grow] = ar; }
        }
        __syncthreads();
    }
}

// ---------------- GCN aggregation: warp/node, fp16 gather, 4-way MLP ----------------
__global__ __launch_bounds__(256) void gcn_agg_h2(const __half* __restrict__ xwh,
                                                  const float* __restrict__ b,
                                                  __half* __restrict__ y, int do_leaky) {
    int node = (blockIdx.x * blockDim.x + threadIdx.x) >> 5;
    int lane = threadIdx.x & 31;
    if (node >= N_NODES) return;
    int s = d_row_ptr[node], e = d_row_ptr[node + 1];
    float4 acc = make_float4(0.f, 0.f, 0.f, 0.f);
    for (int base = s; base < e; base += 32) {
        int j = base + lane;
        int srcL = 0; float nrmL = 0.f;
        if (j < e) { srcL = d_csr_src[j]; nrmL = d_csr_norm[j]; }
        int cnt = min(32, e - base);
        int q = 0;
        for (; q + 4 <= cnt; q += 4) {
            int s0 = __shfl_sync(FULLM, srcL, q);
            int s1 = __shfl_sync(FULLM, srcL, q + 1);
            int s2 = __shfl_sync(FULLM, srcL, q + 2);
            int s3 = __shfl_sync(FULLM, srcL, q + 3);
            float n0 = __shfl_sync(FULLM, nrmL, q);
            float n1 = __shfl_sync(FULLM, nrmL, q + 1);
            float n2 = __shfl_sync(FULLM, nrmL, q + 2);
            float n3 = __shfl_sync(FULLM, nrmL, q + 3);
            uint2 u0 = ((const uint2*)(xwh + (size_t)s0 * CCH))[lane];
            uint2 u1 = ((const uint2*)(xwh + (size_t)s1 * CCH))[lane];
            uint2 u2 = ((const uint2*)(xwh + (size_t)s2 * CCH))[lane];
            uint2 u3 = ((const uint2*)(xwh + (size_t)s3 * CCH))[lane];
            float4 v0 = h4_to_f4(u0);
            acc.x += n0 * v0.x; acc.y += n0 * v0.y; acc.z += n0 * v0.z; acc.w += n0 * v0.w;
            float4 v1 = h4_to_f4(u1);
            acc.x += n1 * v1.x; acc.y += n1 * v1.y; acc.z += n1 * v1.z; acc.w += n1 * v1.w;
            float4 v2 = h4_to_f4(u2);
            acc.x += n2 * v2.x; acc.y += n2 * v2.y; acc.z += n2 * v2.z; acc.w += n2 * v2.w;
            float4 v3 = h4_to_f4(u3);
            acc.x += n3 * v3.x; acc.y += n3 * v3.y; acc.z += n3 * v3.z; acc.w += n3 * v3.w;
        }
        for (; q < cnt; q++) {
            int   sq = __shfl_sync(FULLM, srcL, q);
            float nq = __shfl_sync(FULLM, nrmL, q);
            uint2 u = ((const uint2*)(xwh + (size_t)sq * CCH))[lane];
            float4 v = h4_to_f4(u);
            acc.x += nq * v.x; acc.y += nq * v.y;
            acc.z += nq * v.z; acc.w += nq * v.w;
        }
    }
    float4 bb = ((const float4*)b)[lane];
    acc.x += bb.x; acc.y += bb.y; acc.z += bb.z; acc.w += bb.w;
    if (do_leaky) {
        acc.x = leaky01(acc.x); acc.y = leaky01(acc.y);
        acc.z = leaky01(acc.z); acc.w = leaky01(acc.w);
    }
    ((uint2*)(y + (size_t)node * CCH))[lane] = f4_to_h4(acc);
}

// ---------------- GAT aggregation: warp/node, fp16 gather, 4-way MLP ----------------
__global__ __launch_bounds__(256) void gat_agg_h2(const __half* __restrict__ xwh,
                                                  const float* __restrict__ b,
                                                  __half* __restrict__ y) {
    int node = (blockIdx.x * blockDim.x + threadIdx.x) >> 5;
    int lane = threadIdx.x & 31;
    if (node >= N_NODES) return;
    int s = d_row_ptr[node], e = d_row_ptr[node + 1];
    float arn = d_ar[node];

    float m = -1e30f;
    for (int j = s + lane; j < e; j += 32)
        m = fmaxf(m, leaky20(d_al[d_csr_src[j]] + arn));
    #pragma unroll
    for (int off = 16; off; off >>= 1) m = fmaxf(m, __shfl_xor_sync(FULLM, m, off));

    float denom = 0.f;
    float4 acc = make_float4(0.f, 0.f, 0.f, 0.f);
    for (int base = s; base < e; base += 32) {
        int j = base + lane;
        int srcL = 0; float exL = 0.f;
        if (j < e) {
            srcL = d_csr_src[j];
            exL = __expf(leaky20(d_al[srcL] + arn) - m);
            denom += exL;
        }
        int cnt = min(32, e - base);
        int q = 0;
        for (; q + 4 <= cnt; q += 4) {
            int s0 = __shfl_sync(FULLM, srcL, q);
            int s1 = __shfl_sync(FULLM, srcL, q + 1);
            int s2 = __shfl_sync(FULLM, srcL, q + 2);
            int s3 = __shfl_sync(FULLM, srcL, q + 3);
            float a0 = __shfl_sync(FULLM, exL, q);
            float a1 = __shfl_sync(FULLM, exL, q + 1);
            float a2 = __shfl_sync(FULLM, exL, q + 2);
            float a3 = __shfl_sync(FULLM, exL, q + 3);
            uint2 u0 = ((const uint2*)(xwh + (size_t)s0 * CCH))[lane];
            uint2 u1 = ((const uint2*)(xwh + (size_t)s1 * CCH))[lane];
            uint2 u2 = ((const uint2*)(xwh + (size_t)s2 * CCH))[lane];
            uint2 u3 = ((const uint2*)(xwh + (size_t)s3 * CCH))[lane];
            float4 v0 = h4_to_f4(u0);
            acc.x += a0 * v0.x; acc.y += a0 * v0.y; acc.z += a0 * v0.z; acc.w += a0 * v0.w;
            float4 v1 = h4_to_f4(u1);
            acc.x += a1 * v1.x; acc.y += a1 * v1.y; acc.z += a1 * v1.z; acc.w += a1 * v1.w;
            float4 v2 = h4_to_f4(u2);
            acc.x += a2 * v2.x; acc.y += a2 * v2.y; acc.z += a2 * v2.z; acc.w += a2 * v2.w;
            float4 v3 = h4_to_f4(u3);
            acc.x += a3 * v3.x; acc.y += a3 * v3.y; acc.z += a3 * v3.z; acc.w += a3 * v3.w;
        }
        for (; q < cnt; q++) {
            int   sq = __shfl_sync(FULLM, srcL, q);
            float aq = __shfl_sync(FULLM, exL, q);
            uint2 u = ((const uint2*)(xwh + (size_t)sq * CCH))[lane];
            float4 v = h4_to_f4(u);
            acc.x += aq * v.x; acc.y += aq * v.y;
            acc.z += aq * v.z; acc.w += aq * v.w;
        }
    }
    #pragma unroll
    for (int off = 16; off; off >>= 1) denom += __shfl_xor_sync(FULLM, denom, off);
    float inv = 1.f / denom;

    float4 bb = ((const float4*)b)[lane];
    ((uint2*)(y + (size_t)node * CCH))[lane] =
        f4_to_h4(make_float4(acc.x * inv + bb.x, acc.y * inv + bb.y,
                             acc.z * inv + bb.z, acc.w * inv + bb.w));
}

// ---------------- GraphNorm stats ----------------
__global__ void norm_reduce(const __half* __restrict__ y) {
    int c = threadIdx.x;
    float ls = 0.f, lq = 0.f;
    for (int n = blockIdx.x; n < N_NODES; n += gridDim.x) {
        float v = __half2float(y[(size_t)n * CCH + c]);
        ls += v; lq += v * v;
    }
    atomicAdd(&d_stat[c], ls);
    atomicAdd(&d_stat[CCH + c], lq);
}

__global__ void norm_final(const float* __restrict__ alpha) {
    int c = threadIdx.x;
    float m = d_stat[c] * (1.0f / N_NODES);
    float q = d_stat[CCH + c] * (1.0f / N_NODES);
    float a = alpha[c];
    float var = q - (2.f * a - a * a) * m * m;
    d_shift[c] = a * m;
    d_rstd[c]  = rsqrtf(var + 1e-5f);
    d_stat[c] = 0.f;
    d_stat[CCH + c] = 0.f;
}

// ---------------- output head ----------------
__global__ void gemv_out_f(const __half* __restrict__ x, const __half* __restrict__ yin,
                           const float* __restrict__ gamma, const float* __restrict__ beta,
                           const float* __restrict__ Wout) {
    int g = blockIdx.x * blockDim.x + threadIdx.x;
    int node = g >> 5, lane = g & 31;
    if (node >= N_NODES) return;
    float4 xv = h4_to_f4(((const uint2*)(x + (size_t)node * CCH))[lane]);
    float4 yv = h4_to_f4(((const uint2*)(yin + (size_t)node * CCH))[lane]);
    float4 gm = ((const float4*)gamma)[lane];
    float4 bt = ((const float4*)beta)[lane];
    float4 sh = ((const float4*)d_shift)[lane];
    float4 rs = ((const float4*)d_rstd)[lane];
    float4 w  = ((const float4*)Wout)[lane];
    float vx = xv.x + leaky01(gm.x * (yv.x - sh.x) * rs.x + bt.x);
    float vy = xv.y + leaky01(gm.y * (yv.y - sh.y) * rs.y + bt.y);
    float vz = xv.z + leaky01(gm.z * (yv.z - sh.z) * rs.z + bt.z);
    float vw = xv.w + leaky01(gm.w * (yv.w - sh.w) * rs.w + bt.w);
    float d = vx * w.x + vy * w.y + vz * w.z + vw * w.w;
    #pragma unroll
    for (int off = 16; off; off >>= 1) d += __shfl_down_sync(FULLM, d, off);
    if (lane == 0) d_xw1[node] = d;
}

__global__ void scalar_agg(const float* __restrict__ b_out) {
    int g = blockIdx.x * blockDim.x + threadIdx.x;
    int node = g >> 5, lane = g & 31;
    if (node >= N_NODES) return;
    int s = d_row_ptr[node], e = d_row_ptr[node + 1];
    float acc = 0.f;
    for (int j = s + lane; j < e; j += 32)
        acc += d_csr_norm[j] * d_xw1[d_csr_src[j]];
    #pragma unroll
    for (int off = 16; off; off >>= 1) acc += __shfl_down_sync(FULLM, acc, off);
    if (lane == 0) d_xs[node] = leaky01(acc + b_out[0]);
}

__global__ void fc1_partial(const float* __restrict__ W1) {
    int c = threadIdx.x;
    float acc = 0.f;
    for (int n = blockIdx.x; n < N_NODES; n += gridDim.x)
        acc += d_xs[n] * W1[(long)n * CCH + c];
    atomicAdd(&d_hraw[c], acc);
}

__global__ void fc1_final(const float* __restrict__ b1) {
    int c = threadIdx.x;
    float v = d_hraw[c] + b1[c];
    d_h[c] = v > 0.f ? v : 0.f;
}

__global__ void fc2_k(const float* __restrict__ W2, const float* __restrict__ b2,
                      float* __restrict__ out) {
    __shared__ float hs[CCH];
    int tid = threadIdx.x;
    hs[tid] = d_h[tid];
    __syncthreads();
    int p = blockIdx.x * 128 + tid;
    if (p >= POI_LEN_) return;
    float acc = b2[p];
    #pragma unroll 8
    for (int j = 0; j < CCH; j++)
        acc += hs[j] * W2[(long)j * POI_LEN_ + p];
    out[p] = acc > 0.f ? acc : 0.f;
}

// ---------------- launch ----------------
static inline int div_up(int a, int b) { return (a + b - 1) / b; }

extern "C" void kernel_launch(void* const* d_in, const int* in_sizes, int n_in,
                              void* d_out, int out_size) {
    const int*   poi_ids   = (const int*)  d_in[0];
    const int*   cat_ids   = (const int*)  d_in[1];
    const float* feat3     = (const float*)d_in[2];
    const int*   edge_index= (const int*)  d_in[3];
    const float* edge_w    = (const float*)d_in[4];
    const float* poi_emb   = (const float*)d_in[5];
    const float* cat_emb   = (const float*)d_in[6];
    const float* Win       = (const float*)d_in[7];
    const float* b_in      = (const float*)d_in[8];
    const float* gcn_W     = (const float*)d_in[9];
    const float* gcn_b     = (const float*)d_in[10];
    const float* gn_gamma  = (const float*)d_in[11];
    const float* gn_beta   = (const float*)d_in[12];
    const float* gn_alpha  = (const float*)d_in[13];
    const float* gat_W     = (const float*)d_in[14];
    const float* gat_asrc  = (const float*)d_in[15];
    const float* gat_adst  = (const float*)d_in[16];
    const float* gat_b     = (const float*)d_in[17];
    const float* Wout      = (const float*)d_in[18];
    const float* b_out     = (const float*)d_in[19];
    const float* fc_W1     = (const float*)d_in[20];
    const float* fc_b1     = (const float*)d_in[21];
    const float* fc_W2     = (const float*)d_in[22];
    const float* fc_b2     = (const float*)d_in[23];
    float* out = (float*)d_out;

    __half *x_p, *y_p, *xwh_p, *feath_p;
    cudaGetSymbolAddress((void**)&x_p,  d_x);
    cudaGetSymbolAddress((void**)&y_p,  d_y);
    cudaGetSymbolAddress((void**)&xwh_p, d_xwh);
    cudaGetSymbolAddress((void**)&feath_p, d_feath);

    const int warpGrid = div_up(N_NODES * 32, 256);
    const int edgeGrid = div_up(NEDGES, 256);
    const int gemmGrid = N_PAD / GM;               // 600
    const int aggGrid  = div_up(N_NODES, 8);       // warp per node

    feat_k<<<N_NODES, 128>>>(poi_ids, cat_ids, feat3, poi_emb, cat_emb);
    init_k<<<div_up(N_NODES, 256), 256>>>();
    hist_k<<<edgeGrid, 256>>>(edge_index);
    gemm_h16_db<<<gemmGrid, 256>>>(feath_p, Win, xwh_p, N_NODES, FD_PAD, FEAT_DIM,
                                   nullptr, nullptr, nullptr, nullptr, 0,
                                   nullptr, nullptr, 0);
    scan_k<<<1, 1024>>>();
    selfloop_k<<<div_up(N_NODES, 256), 256>>>();
    scatter_k<<<edgeGrid, 256>>>(edge_index, edge_w);
    deg_k<<<warpGrid, 256>>>();
    csnorm_k<<<warpGrid, 256>>>();

    gcn_agg_h2<<<aggGrid, 256>>>(xwh_p, b_in, x_p, 1);

    for (int l = 0; l < NLAYERS; l++) {
        // GCN half: gemm (prev GAT norm fused for l>0)
        if (l == 0)
            gemm_h16_db<<<gemmGrid, 256>>>(x_p, gcn_W, xwh_p, N_NODES, CCH, CCH,
                                           nullptr, nullptr, nullptr, nullptr, 0,
                                           nullptr, nullptr, 0);
        else
            gemm_h16_db<<<gemmGrid, 256>>>(nullptr, gcn_W + l * CCH * CCH, xwh_p,
                                           N_NODES, CCH, CCH,
                                           y_p, x_p,
                                           gn_gamma + (l - 1) * CCH, gn_beta + (l - 1) * CCH, 1,
                                           nullptr, nullptr, 0);
        gcn_agg_h2<<<aggGrid, 256>>>(xwh_p, gcn_b + l * CCH, y_p, 0);
        norm_reduce<<<592, 128>>>(y_p);
        norm_final<<<1, 128>>>(gn_alpha + l * CCH);

        // GAT half: gemm with fused GCN norm + alar epilogue
        gemm_h16_db<<<gemmGrid, 256>>>(nullptr, gat_W + l * CCH * CCH, xwh_p,
                                       N_NODES, CCH, CCH,
                                       y_p, x_p,
                                       gn_gamma + l * CCH, gn_beta + l * CCH, 1,
                                       gat_asrc + l * CCH, gat_adst + l * CCH, 1);
        gat_agg_h2<<<aggGrid, 256>>>(xwh_p, gat_b + l * CCH, y_p);
        norm_reduce<<<592, 128>>>(y_p);
        norm_final<<<1, 128>>>(gn_alpha + l * CCH);
    }

    // output conv (final norm fused) + FC head
    gemv_out_f<<<warpGrid, 256>>>(x_p, y_p, gn_gamma + 4 * CCH, gn_beta + 4 * CCH, Wout);
    scalar_agg<<<warpGrid, 256>>>(b_out);
    fc1_partial<<<592, 128>>>(fc_W1);
    fc1_final<<<1, 128>>>(fc_b1);
    fc2_k<<<div_up(POI_LEN_, 128), 128>>>(fc_W2, fc_b2, out);
}